// round 14
// baseline (speedup 1.0000x reference)
#include <cuda_runtime.h>
#include <cstdint>

#if defined(__CUDA_ARCH_FEAT_SM100_ALL) || defined(__CUDA_ARCH_FEAT_SM103_ALL) || defined(__CUDA_ARCH_FEAT_SM101_ALL) || defined(__CUDA_ARCH_SPECIFIC__)
#define HAS_TC 1
#else
#define HAS_TC 0
#endif

// fallback float scratch
__device__ float g_Q [4*8*2048*64];
__device__ float g_K [4*8*2048*64];
__device__ float g_Vt[4*8*64*2048];
// shared
__device__ float g_AO[4*2048*512];
// TC-path scratch
__device__ uint32_t g_Qt [4*8*2048*64];     // prescaled tf32 (B,H,S,dk)
__device__ uint32_t g_Kt [4*8*16*8192];     // swizzled 128x64 tile blocks
__device__ uint32_t g_Vtt[4*8*16*8192];     // swizzled 64x128 tile blocks
__device__ uint32_t g_Whi[4*512*512];       // chunk-blocked pre-swizzled
__device__ uint32_t g_Wlo[4*512*512];
__device__ uint32_t g_Xt [8192*512];        // x chunk-blocked pre-swizzled tf32
__device__ uint32_t g_Ct [8192*512];        // c chunk-blocked pre-swizzled tf32

#if HAS_TC
__device__ __forceinline__ uint32_t elect_one_pred() {
    uint32_t p;
    asm volatile("{\n\t.reg .pred p;\n\telect.sync _|p, 0xFFFFFFFF;\n\tselp.b32 %0,1,0,p;\n\t}" : "=r"(p));
    return p;
}
__device__ __forceinline__ uint32_t smem_to_u32(const void* p) {
    uint32_t a;
    asm("{ .reg .u64 t; cvta.to.shared.u64 t, %1; cvt.u32.u64 %0, t; }" : "=r"(a) : "l"(p));
    return a;
}
#define TCGEN05_ALLOC(s, n) asm volatile("tcgen05.alloc.cta_group::1.sync.aligned.shared::cta.b32 [%0], %1;" :: "r"((uint32_t)(s)), "r"((uint32_t)(n)) : "memory")
#define TCGEN05_RELINQ() asm volatile("tcgen05.relinquish_alloc_permit.cta_group::1.sync.aligned;")
#define TCGEN05_DEALLOC(t, n) asm volatile("tcgen05.dealloc.cta_group::1.sync.aligned.b32 %0, %1;" :: "r"(t), "r"((uint32_t)(n)))
#define TCGEN05_COMMIT(m) asm volatile("tcgen05.commit.cta_group::1.mbarrier::arrive::one.shared::cluster.b64 [%0];" :: "r"((uint32_t)(m)) : "memory")
#define TCGEN05_WAIT_LD() asm volatile("tcgen05.wait::ld.sync.aligned;" ::: "memory")
#define TCGEN05_WAIT_ST() asm volatile("tcgen05.wait::st.sync.aligned;" ::: "memory")
#define TC_FENCE_BEFORE() asm volatile("tcgen05.fence::before_thread_sync;" ::: "memory")
#define TC_FENCE_AFTER()  asm volatile("tcgen05.fence::after_thread_sync;" ::: "memory")
#define FENCE_ASYNC() asm volatile("fence.proxy.async.shared::cta;" ::: "memory")
#define MBAR_INIT(m, c) asm volatile("mbarrier.init.shared.b64 [%0], %1;" :: "r"((uint32_t)(m)), "r"((uint32_t)(c)) : "memory")
#define MBAR_INVAL(m) asm volatile("mbarrier.inval.shared.b64 [%0];" :: "r"((uint32_t)(m)) : "memory")
#define MBAR_EXPECT(m, bytes) asm volatile("mbarrier.arrive.expect_tx.shared.b64 _, [%0], %1;" :: "r"((uint32_t)(m)), "r"((uint32_t)(bytes)) : "memory")
#define BULK_CP(dst, src, bytes, mbar) \
    asm volatile("cp.async.bulk.shared::cluster.global.mbarrier::complete_tx::bytes [%0], [%1], %2, [%3];" \
        :: "r"((uint32_t)(dst)), "l"(src), "r"((uint32_t)(bytes)), "r"((uint32_t)(mbar)) : "memory")
#define MBAR_WAIT(m, par) do { \
    uint32_t _m=(uint32_t)(m), _p=(uint32_t)(par), _d; \
    asm volatile("{\n\t.reg .pred p;\n\tmbarrier.try_wait.parity.acquire.cta.shared::cta.b64 p, [%1], %2;\n\tselp.b32 %0,1,0,p;\n\t}" : "=r"(_d) : "r"(_m), "r"(_p) : "memory"); \
    if (!_d) { asm volatile("{\n\t.reg .pred P1;\n\tWL_%=:\n\tmbarrier.try_wait.parity.acquire.cta.shared::cta.b64 P1, [%0], %1, 0x989680;\n\t@P1 bra.uni WD_%=;\n\tbra.uni WL_%=;\n\tWD_%=:\n\t}" :: "r"(_m), "r"(_p) : "memory"); } } while (0)

#define LDTM32(r, a) asm volatile("tcgen05.ld.sync.aligned.32x32b.x32.b32 " \
    "{%0,%1,%2,%3,%4,%5,%6,%7,%8,%9,%10,%11,%12,%13,%14,%15,%16,%17,%18,%19,%20,%21,%22,%23,%24,%25,%26,%27,%28,%29,%30,%31}, [%32];" \
    : "=r"((r)[0]),"=r"((r)[1]),"=r"((r)[2]),"=r"((r)[3]),"=r"((r)[4]),"=r"((r)[5]),"=r"((r)[6]),"=r"((r)[7]), \
      "=r"((r)[8]),"=r"((r)[9]),"=r"((r)[10]),"=r"((r)[11]),"=r"((r)[12]),"=r"((r)[13]),"=r"((r)[14]),"=r"((r)[15]), \
      "=r"((r)[16]),"=r"((r)[17]),"=r"((r)[18]),"=r"((r)[19]),"=r"((r)[20]),"=r"((r)[21]),"=r"((r)[22]),"=r"((r)[23]), \
      "=r"((r)[24]),"=r"((r)[25]),"=r"((r)[26]),"=r"((r)[27]),"=r"((r)[28]),"=r"((r)[29]),"=r"((r)[30]),"=r"((r)[31]) : "r"(a))
#define STTM32(a, r) asm volatile("tcgen05.st.sync.aligned.32x32b.x32.b32 [%0], " \
    "{%1,%2,%3,%4,%5,%6,%7,%8,%9,%10,%11,%12,%13,%14,%15,%16,%17,%18,%19,%20,%21,%22,%23,%24,%25,%26,%27,%28,%29,%30,%31,%32};" \
    :: "r"(a), "r"((r)[0]),"r"((r)[1]),"r"((r)[2]),"r"((r)[3]),"r"((r)[4]),"r"((r)[5]),"r"((r)[6]),"r"((r)[7]), \
       "r"((r)[8]),"r"((r)[9]),"r"((r)[10]),"r"((r)[11]),"r"((r)[12]),"r"((r)[13]),"r"((r)[14]),"r"((r)[15]), \
       "r"((r)[16]),"r"((r)[17]),"r"((r)[18]),"r"((r)[19]),"r"((r)[20]),"r"((r)[21]),"r"((r)[22]),"r"((r)[23]), \
       "r"((r)[24]),"r"((r)[25]),"r"((r)[26]),"r"((r)[27]),"r"((r)[28]),"r"((r)[29]),"r"((r)[30]),"r"((r)[31]) : "memory")

static constexpr uint64_t DESC_BASE =
    (uint64_t(2) << 61) | (uint64_t(1) << 46) | (uint64_t(64) << 32) | (uint64_t(1) << 16);
#define MAKE_DESC(b) (DESC_BASE | ((uint64_t)((b) >> 4) & 0x3FFF))
#define SWZ(o) ((o) ^ (((o) >> 3) & 0x70))

__device__ __forceinline__ constexpr uint32_t idesc_tf32(int M, int N) {
    return (1u << 4) | (2u << 7) | (2u << 10) | ((uint32_t)(N / 8) << 17) | ((uint32_t)(M / 16) << 24);
}
__device__ __forceinline__ void mma_ss(uint32_t d, uint64_t ad, uint64_t bd, uint32_t id, uint32_t en) {
    asm volatile("{\n\t.reg .pred p;\n\tsetp.ne.u32 p, %5, 0;\n\t"
        "tcgen05.mma.cta_group::1.kind::tf32 [%0], %1, %2, %3, {%4,%4,%4,%4}, p;\n\t}"
        :: "r"(d), "l"(ad), "l"(bd), "r"(id), "r"(0u), "r"(en) : "memory");
}
__device__ __forceinline__ void mma_ts(uint32_t d, uint32_t at, uint64_t bd, uint32_t id, uint32_t en) {
    asm volatile("{\n\t.reg .pred p;\n\tsetp.ne.u32 p, %5, 0;\n\t"
        "tcgen05.mma.cta_group::1.kind::tf32 [%0], [%1], %2, %3, {%4,%4,%4,%4}, p;\n\t}"
        :: "r"(d), "r"(at), "l"(bd), "r"(id), "r"(0u), "r"(en) : "memory");
}
__device__ __forceinline__ uint32_t f2tf32(float x) {
    uint32_t r; asm("cvt.rna.tf32.f32 %0, %1;" : "=r"(r) : "f"(x)); return r;
}
__device__ __forceinline__ void split_tf32(float x, uint32_t& hi, uint32_t& lo) {
    hi = __float_as_uint(x) & 0xFFFFE000u;
    lo = f2tf32(x - __uint_as_float(hi));
}
__device__ __forceinline__ uint32_t blk_off(int row, int col, int atom_rows) {
    return (uint32_t)((((col >> 5) * atom_rows + (row >> 3)) * 8 + (row & 7)) * 128 + ((col & 31) << 2));
}
#endif  // HAS_TC

// ---- W pre-split into chunk-blocked pre-swizzled hi/lo blocks ----
__global__ __launch_bounds__(256) void presplit_w(
    const float* __restrict__ Wq, const float* __restrict__ Wk,
    const float* __restrict__ Wv, const float* __restrict__ Wo,
    uint32_t* __restrict__ whi, uint32_t* __restrict__ wlo)
{
#if HAS_TC
    const int m = blockIdx.y;
    const float* W = (m == 0) ? Wq : (m == 1) ? Wk : (m == 2) ? Wv : Wo;
    const int row_g = blockIdx.x * 4 + (threadIdx.x >> 6);
    const int k0 = (threadIdx.x & 63) * 8;
    const int bn_tile = row_g >> 7, row = row_g & 127;
    const size_t blk_base = ((size_t)m * 4 + bn_tile) * 16;
#pragma unroll
    for (int p = 0; p < 2; p++) {
        const int k = k0 + p * 4;
        float4 v = *(const float4*)(W + (size_t)row_g * 512 + k);
        uint4 h, l;
        split_tf32(v.x, h.x, l.x); split_tf32(v.y, h.y, l.y);
        split_tf32(v.z, h.z, l.z); split_tf32(v.w, h.w, l.w);
        const int ch = k >> 5, col = k & 31;
        const uint32_t off = SWZ((uint32_t)(row * 128 + col * 4)) >> 2;
        *(uint4*)(whi + (blk_base + ch) * 4096 + off) = h;
        *(uint4*)(wlo + (blk_base + ch) * 4096 + off) = l;
    }
#endif
}

// ---- x/c pre-convert to chunk-blocked pre-swizzled single tf32 ----
__global__ __launch_bounds__(256) void preconv_a(
    const float* __restrict__ x, const float* __restrict__ c,
    uint32_t* __restrict__ xt, uint32_t* __restrict__ ct)
{
#if HAS_TC
    const float* A = blockIdx.y ? c : x;
    uint32_t* O = blockIdx.y ? ct : xt;
    const int row_g = blockIdx.x * 4 + (threadIdx.x >> 6);   // 0..8191
    const int k0 = (threadIdx.x & 63) * 8;
    const int bm_tile = row_g >> 7, row = row_g & 127;
#pragma unroll
    for (int p = 0; p < 2; p++) {
        const int k = k0 + p * 4;
        float4 v = *(const float4*)(A + (size_t)row_g * 512 + k);
        uint4 u;
        u.x = f2tf32(v.x); u.y = f2tf32(v.y); u.z = f2tf32(v.z); u.w = f2tf32(v.w);
        const int ch = k >> 5, col = k & 31;
        const uint32_t off = SWZ((uint32_t)(row * 128 + col * 4)) >> 2;
        *(uint4*)(O + ((size_t)bm_tile * 16 + ch) * 4096 + off) = u;
    }
#endif
}

#if HAS_TC
// -------- GEMM core: ABULK=1 -> A,W all via cp.async.bulk (no syncs in loop) --------
// MODE 0: float row-major; 5: Q tf32 prescaled(*log2e); 3: K swizzled; 4: V swizzled
template<int ABULK>
__device__ __forceinline__ void gemm_core_tc(
    const float* __restrict__ A, const uint32_t* __restrict__ at,
    const uint32_t* __restrict__ whi, const uint32_t* __restrict__ wlo,
    const float* __restrict__ bias, void* __restrict__ outv,
    int MODE, char* sm, int bm, int bn)
{
    const uint32_t sb = smem_to_u32(sm);
    const int tid = threadIdx.x, wid = tid >> 5, lid = tid & 31;
    const uint32_t MBM0 = sb + 8, MBM1 = sb + 16, MBW0 = sb + 24, MBW1 = sb + 32;
    const uint32_t ID = idesc_tf32(128, 128);

    if (wid == 0) { TCGEN05_ALLOC(sb, 128); TCGEN05_RELINQ(); }
    if (tid == 0) { MBAR_INIT(MBM0, 1); MBAR_INIT(MBM1, 1); MBAR_INIT(MBW0, 1); MBAR_INIT(MBW1, 1); }
    __syncthreads();
    uint32_t tb;
    asm volatile("ld.shared.b32 %0, [%1];" : "=r"(tb) : "r"(sb));

    const uint32_t* wbh = whi + (size_t)(bn >> 7) * 16 * 4096;
    const uint32_t* wbl = wlo + (size_t)(bn >> 7) * 16 * 4096;
    const uint32_t* abt = ABULK ? (at + (size_t)(bm >> 7) * 16 * 4096) : nullptr;
    const int ar = tid >> 3, ac = (tid & 7) << 2;
    float4 a4[4];
    if (!ABULK) {
#pragma unroll
        for (int t = 0; t < 4; t++)
            a4[t] = *(const float4*)(A + (size_t)(bm + ar + t * 32) * 512 + ac);
    }

    for (int ch = 0; ch < 16; ch++) {
        if (ch >= 2) MBAR_WAIT((ch & 1) ? MBM1 : MBM0, ((ch - 2) >> 1) & 1);
        const uint32_t BUF = sb + 1024 + (uint32_t)(ch & 1) * 49152;
        const uint32_t mw = (ch & 1) ? MBW1 : MBW0;
        if (ABULK) {
            if (tid == 0) {
                MBAR_EXPECT(mw, 49152);
                BULK_CP(BUF,         abt + (size_t)ch * 4096, 16384, mw);
                BULK_CP(BUF + 16384, wbh + (size_t)ch * 4096, 16384, mw);
                BULK_CP(BUF + 32768, wbl + (size_t)ch * 4096, 16384, mw);
            }
        } else {
            if (tid == 0) {
                MBAR_EXPECT(mw, 32768);
                BULK_CP(BUF + 16384, wbh + (size_t)ch * 4096, 16384, mw);
                BULK_CP(BUF + 32768, wbl + (size_t)ch * 4096, 16384, mw);
            }
#pragma unroll
            for (int t = 0; t < 4; t++) {
                uint32_t o = SWZ((uint32_t)((ar + t * 32) * 128 + ac * 4));
                uint4 h;
                h.x = f2tf32(a4[t].x); h.y = f2tf32(a4[t].y);
                h.z = f2tf32(a4[t].z); h.w = f2tf32(a4[t].w);
                *(uint4*)(sm + (BUF - sb) + o) = h;
            }
            FENCE_ASYNC();
            __syncthreads();
        }
        MBAR_WAIT(mw, (ch >> 1) & 1);
        if (wid == 0 && elect_one_pred()) {
            TC_FENCE_AFTER();
            uint64_t ad = MAKE_DESC(BUF), wh = MAKE_DESC(BUF + 16384), wl = MAKE_DESC(BUF + 32768);
#pragma unroll
            for (int ks = 0; ks < 4; ks++) {
                mma_ss(tb, ad + ks * 2, wh + ks * 2, ID, (ch | ks) ? 1u : 0u);
                mma_ss(tb, ad + ks * 2, wl + ks * 2, ID, 1u);
            }
            TCGEN05_COMMIT((ch & 1) ? MBM1 : MBM0);
        }
        if (!ABULK && ch < 15) {
            const int k0 = (ch + 1) * 32;
#pragma unroll
            for (int t = 0; t < 4; t++)
                a4[t] = *(const float4*)(A + (size_t)(bm + ar + t * 32) * 512 + k0 + ac);
        }
    }
    MBAR_WAIT(MBM1, 1);
    TC_FENCE_AFTER();
    {
        const int m = bm + ((wid & 3) << 5) + lid;
        const int b = m >> 11, s = m & 2047;
#pragma unroll
        for (int cc = 0; cc < 2; cc++) {
            const int c0 = ((wid >> 2) << 6) + cc * 32;
            uint32_t r[32];
            LDTM32(r, tb + c0);
            TCGEN05_WAIT_LD();
            if (MODE == 0) {
                float* out = (float*)outv;
#pragma unroll
                for (int j = 0; j < 32; j += 4) {
                    const int n = bn + c0 + j;
                    float4 v;
                    v.x = __uint_as_float(r[j + 0]) + bias[n + 0];
                    v.y = __uint_as_float(r[j + 1]) + bias[n + 1];
                    v.z = __uint_as_float(r[j + 2]) + bias[n + 2];
                    v.w = __uint_as_float(r[j + 3]) + bias[n + 3];
                    *(float4*)(out + (size_t)m * 512 + n) = v;
                }
            } else if (MODE == 5) {
                uint32_t* qt = (uint32_t*)outv;
                const float qs = 0.125f * 1.44269504088896f;   // fold log2e
#pragma unroll
                for (int j = 0; j < 32; j += 4) {
                    const int n = bn + c0 + j;
                    const int hh = n >> 6, dk = n & 63;
                    uint4 u;
                    u.x = f2tf32((__uint_as_float(r[j + 0]) + bias[n + 0]) * qs);
                    u.y = f2tf32((__uint_as_float(r[j + 1]) + bias[n + 1]) * qs);
                    u.z = f2tf32((__uint_as_float(r[j + 2]) + bias[n + 2]) * qs);
                    u.w = f2tf32((__uint_as_float(r[j + 3]) + bias[n + 3]) * qs);
                    *(uint4*)(qt + (((size_t)(b * 8 + hh) * 2048 + s) << 6) + dk) = u;
                }
            } else if (MODE == 3) {
                uint32_t* kt = (uint32_t*)outv;
                const int tile = s >> 7, rr = s & 127;
#pragma unroll
                for (int j = 0; j < 32; j += 4) {
                    const int n = bn + c0 + j;
                    const int hh = n >> 6, dk = n & 63;
                    uint4 u;
                    u.x = f2tf32(__uint_as_float(r[j + 0]) + bias[n + 0]);
                    u.y = f2tf32(__uint_as_float(r[j + 1]) + bias[n + 1]);
                    u.z = f2tf32(__uint_as_float(r[j + 2]) + bias[n + 2]);
                    u.w = f2tf32(__uint_as_float(r[j + 3]) + bias[n + 3]);
                    *(uint4*)(kt + ((size_t)((b * 8 + hh) * 16 + tile) << 13)
                                 + (SWZ(blk_off(rr, dk, 16)) >> 2)) = u;
                }
            } else {  // MODE 4: V
                uint32_t* vt = (uint32_t*)outv;
                const int tile = s >> 7, colv = s & 127;
#pragma unroll
                for (int j = 0; j < 32; j++) {
                    const int n = bn + c0 + j;
                    const int hh = n >> 6, dk = n & 63;
                    vt[((size_t)((b * 8 + hh) * 16 + tile) << 13)
                       + (SWZ(blk_off(dk, colv, 8)) >> 2)] =
                        f2tf32(__uint_as_float(r[j]) + bias[n]);
                }
            }
        }
    }
    TC_FENCE_BEFORE();
    __syncthreads();
    if (tid == 0) { MBAR_INVAL(MBM0); MBAR_INVAL(MBM1); MBAR_INVAL(MBW0); MBAR_INVAL(MBW1); }
    __syncthreads();
    if (wid == 0) TCGEN05_DEALLOC(tb, 128);
}
#endif  // HAS_TC

#if !HAS_TC
__device__ __forceinline__ void gemm_core_fb(
    const float* __restrict__ A, const float* __restrict__ W,
    const float* __restrict__ bias, float* __restrict__ out,
    int MODE, float* smf, int bm, int bn)
{
    float* As = smf;
    float* Bs = smf + 128 * 17;
    const int tid = threadIdx.x;
    const int r0 = (tid >> 4) * 8, c0 = (tid & 15) * 8;
    float acc[8][8];
#pragma unroll
    for (int i = 0; i < 8; i++)
#pragma unroll
        for (int j = 0; j < 8; j++) acc[i][j] = 0.f;
    for (int k0 = 0; k0 < 512; k0 += 16) {
#pragma unroll
        for (int t = 0; t < 8; t++) {
            int lin = tid + t * 256;
            int r = lin >> 4, k = lin & 15;
            As[r * 17 + k] = A[(size_t)(bm + r) * 512 + k0 + k];
            Bs[r * 17 + k] = W[(size_t)(bn + r) * 512 + k0 + k];
        }
        __syncthreads();
#pragma unroll
        for (int k = 0; k < 16; k++) {
            float a8[8], b8[8];
#pragma unroll
            for (int i = 0; i < 8; i++) a8[i] = As[(r0 + i) * 17 + k];
#pragma unroll
            for (int j = 0; j < 8; j++) b8[j] = Bs[(c0 + j) * 17 + k];
#pragma unroll
            for (int i = 0; i < 8; i++)
#pragma unroll
                for (int j = 0; j < 8; j++) acc[i][j] = fmaf(a8[i], b8[j], acc[i][j]);
        }
        __syncthreads();
    }
#pragma unroll
    for (int i = 0; i < 8; i++) {
        int m = bm + r0 + i;
#pragma unroll
        for (int j = 0; j < 8; j++) {
            int n = bn + c0 + j;
            float v = acc[i][j] + bias[n];
            if (MODE == 0) out[(size_t)m * 512 + n] = v;
            else {
                int b = m >> 11, s = m & 2047, h = n >> 6, dk = n & 63;
                if (MODE == 1) out[(((size_t)(b * 8 + h) * 2048 + s) << 6) + dk] = v;
                else           out[((size_t)(b * 8 + h) * 64 + dk) * 2048 + s] = v;
            }
        }
    }
}
#endif

__global__ __launch_bounds__(256) void gemm_qkv(
    const float* __restrict__ x, const float* __restrict__ c,
    const float* __restrict__ Wq, const float* __restrict__ bq,
    const float* __restrict__ Wk, const float* __restrict__ bk,
    const float* __restrict__ Wv, const float* __restrict__ bv,
    const uint32_t* __restrict__ whi, const uint32_t* __restrict__ wlo,
    const uint32_t* __restrict__ xt, const uint32_t* __restrict__ ct,
    float* __restrict__ qp, float* __restrict__ kp, float* __restrict__ vp,
    uint32_t* __restrict__ qt, uint32_t* __restrict__ kt, uint32_t* __restrict__ vtt)
{
    const int z = blockIdx.z;
    const float* bias = (z == 0) ? bq : (z == 1) ? bk : bv;
#if HAS_TC
    const uint32_t* at = (z == 0) ? xt : ct;
    void* out = (z == 0) ? (void*)qt : (z == 1) ? (void*)kt : (void*)vtt;
    const int MODE = (z == 0) ? 5 : (z == 1) ? 3 : 4;
    extern __shared__ char sm[];
    gemm_core_tc<1>(nullptr, at, whi + (size_t)z * 262144, wlo + (size_t)z * 262144,
                    bias, out, MODE, sm, blockIdx.x * 128, blockIdx.y * 128);
#else
    const float* A = (z == 0) ? x : c;
    const float* W = (z == 0) ? Wq : (z == 1) ? Wk : Wv;
    float* out = (z == 0) ? qp : (z == 1) ? kp : vp;
    const int MODE = (z == 2) ? 2 : 1;
    extern __shared__ float smf[];
    gemm_core_fb(A, W, bias, out, MODE, smf, blockIdx.x * 128, blockIdx.y * 128);
#endif
}

__global__ __launch_bounds__(256) void gemm_o(
    const float* __restrict__ A, const float* __restrict__ W,
    const uint32_t* __restrict__ whi, const uint32_t* __restrict__ wlo,
    const float* __restrict__ bias, float* __restrict__ out)
{
#if HAS_TC
    extern __shared__ char sm[];
    gemm_core_tc<0>(A, nullptr, whi + (size_t)3 * 262144, wlo + (size_t)3 * 262144,
                    bias, out, 0, sm, blockIdx.x * 128, blockIdx.y * 128);
#else
    extern __shared__ float smf[];
    gemm_core_fb(A, W, bias, out, 0, smf, blockIdx.x * 128, blockIdx.y * 128);
#endif
}

// ===================== attention (R10 + split-S + exp2) =====================
// TMEM (256): Q 0-63 | S/P in-place 64-191 | O 192-255
__global__ __launch_bounds__(256, 2) void attn_tf32(
    const float* __restrict__ rel,
    const uint32_t* __restrict__ qt, const uint32_t* __restrict__ kt,
    const uint32_t* __restrict__ vtt,
    const float* __restrict__ Qg, const float* __restrict__ Kg,
    const float* __restrict__ Vtg, float* __restrict__ AO)
{
#if HAS_TC
    extern __shared__ char sm[];
    const uint32_t sb = smem_to_u32(sm);
    const int tid = threadIdx.x, wid = tid >> 5, lid = tid & 31;
    const int lg = wid & 3, half = wid >> 2;
    const int q0 = blockIdx.x * 128, bh = blockIdx.y, h = bh & 7;
    const uint32_t MBS0 = sb + 8, MBS1 = sb + 16, MBPV = sb + 24;
    const uint32_t MBK0 = sb + 32, MBK1 = sb + 40, MBV = sb + 48;
    float* bias_f = (float*)(sm + 64);
    const uint32_t KB0 = sb + 2048, KB1 = KB0 + 32768, VB = KB1 + 32768;
    const uint32_t ID_S64 = idesc_tf32(128, 64), ID_PV = idesc_tf32(128, 64);
    const int QB = 0, SPB = 64, OB = 192;

    if (wid == 0) { TCGEN05_ALLOC(sb, 256); TCGEN05_RELINQ(); }
    if (tid == 0) {
        MBAR_INIT(MBS0, 1); MBAR_INIT(MBS1, 1); MBAR_INIT(MBPV, 1);
        MBAR_INIT(MBK0, 1); MBAR_INIT(MBK1, 1); MBAR_INIT(MBV, 1);
    }
    __syncthreads();
    uint32_t tb;
    asm volatile("ld.shared.b32 %0, [%1];" : "=r"(tb) : "r"(sb));

    const uint32_t* ktb = kt + ((size_t)bh * 16 << 13);
    const uint32_t* vtb = vtt + ((size_t)bh * 16 << 13);

    if (tid == 0) {
        MBAR_EXPECT(MBK0, 32768);
        BULK_CP(KB0, ktb, 32768, MBK0);
        MBAR_EXPECT(MBV, 32768);
        BULK_CP(VB, vtb, 32768, MBV);
    }
    if (tid < 128) {                                  // Q -> TMEM (prescaled, log2e folded)
        const uint32_t* qrow = qt + (((size_t)bh * 2048 + q0 + tid) << 6);
        uint32_t qh[32];
#pragma unroll
        for (int p = 0; p < 2; p++) {
#pragma unroll
            for (int j4 = 0; j4 < 8; j4++)
                *(uint4*)(qh + j4 * 4) = *(const uint4*)(qrow + p * 32 + j4 * 4);
            STTM32(tb + QB + p * 32 + ((uint32_t)(tid >> 5) << 21), qh);
        }
        TCGEN05_WAIT_ST();
    }
    TC_FENCE_BEFORE();
    __syncthreads();

    float l_acc = 0.f;
    const int qr = lg * 32 + lid;

    for (int t = 0; t < 16; t++) {
        for (int u = tid; u < 255; u += 256)          // bias * log2e
            bias_f[u] = rel[(size_t)(q0 - t * 128 + 1920 + u) * 8 + h] * 1.44269504088896f;

        MBAR_WAIT((t & 1) ? MBK1 : MBK0, (t >> 1) & 1);
        if (wid == 0 && elect_one_pred()) {           // split S: two N=64 halves
            TC_FENCE_AFTER();
            uint64_t kd = MAKE_DESC((t & 1) ? KB1 : KB0);
#pragma unroll
            for (int ks = 0; ks < 8; ks++) {
                uint64_t ko = (uint64_t)((ks >> 2) * 1024 + (ks & 3) * 2);
                mma_ts(tb + SPB, tb + QB + ks * 8, kd + ko, ID_S64, ks ? 1u : 0u);
            }
            TCGEN05_COMMIT(MBS0);
#pragma unroll
            for (int ks = 0; ks < 8; ks++) {
                uint64_t ko = (uint64_t)((ks >> 2) * 1024 + (ks & 3) * 2);
                mma_ts(tb + SPB + 64, tb + QB + ks * 8, kd + 512 + ko, ID_S64, ks ? 1u : 0u);
            }
            TCGEN05_COMMIT(MBS1);
        }
        if (tid == 0 && t < 15) {
            const uint32_t KBn = ((t + 1) & 1) ? KB1 : KB0;
            MBAR_EXPECT(((t + 1) & 1) ? MBK1 : MBK0, 32768);
            BULK_CP(KBn, ktb + ((size_t)(t + 1) << 13), 32768, ((t + 1) & 1) ? MBK1 : MBK0);
        }
        if (t > 0) {
            MBAR_WAIT(MBPV, (t - 1) & 1);
            if (tid == 0) {
                MBAR_EXPECT(MBV, 32768);
                BULK_CP(VB, vtb + ((size_t)t << 13), 32768, MBV);
            }
        }
        __syncthreads();

        // softmax on own half: warps 0-3 wait MBS0 (cols 0-63), warps 4-7 MBS1
        MBAR_WAIT(half ? MBS1 : MBS0, t & 1);
        TC_FENCE_AFTER();
#pragma unroll
        for (int cc = 0; cc < 2; cc++) {
            const int c = half * 2 + cc;
            uint32_t r[32];
            LDTM32(r, tb + SPB + 32 * c);
            TCGEN05_WAIT_LD();
            uint32_t pr[32];
#pragma unroll
            for (int j = 0; j < 32; j++) {
                float s = __uint_as_float(r[j]) + bias_f[qr - (32 * c + j) + 127];
                float p = exp2f(s);
                l_acc += p;
                pr[j] = f2tf32(p);
            }
            STTM32(tb + SPB + 32 * c + ((uint32_t)lg << 21), pr);
        }
        TCGEN05_WAIT_ST();
        TC_FENCE_BEFORE();
        __syncthreads();

        MBAR_WAIT(MBV, t & 1);
        if (wid == 0 && elect_one_pred()) {
            TC_FENCE_AFTER();
            uint64_t vd = MAKE_DESC(VB);
#pragma unroll
            for (int ks = 0; ks < 16; ks++) {
                uint64_t vo = (uint64_t)((ks >> 2) * 512 + (ks & 3) * 2);
                mma_ts(tb + OB, tb + SPB + ks * 8, vd + vo, ID_PV, (t == 0 && ks == 0) ? 0u : 1u);
            }
            TCGEN05_COMMIT(MBPV);
        }
    }
    MBAR_WAIT(MBPV, 1);

    __syncthreads();
    float* l_sh = (float*)(sm + 64);
    l_sh[tid] = l_acc;
    __syncthreads();
    const float inv = 1.0f / (l_sh[tid & 127] + l_sh[(tid & 127) + 128]);

    TC_FENCE_AFTER();
    {
        uint32_t r[32];
        LDTM32(r, tb + OB + 32 * half);
        TCGEN05_WAIT_LD();
        const int b = bh >> 3;
        float* dst = AO + ((size_t)b * 2048 + q0 + qr) * 512 + h * 64 + 32 * half;
#pragma unroll
        for (int j = 0; j < 32; j++) dst[j] = __uint_as_float(r[j]) * inv;
    }
    TC_FENCE_BEFORE();
    __syncthreads();
    if (tid == 0) {
        MBAR_INVAL(MBS0); MBAR_INVAL(MBS1); MBAR_INVAL(MBPV);
        MBAR_INVAL(MBK0); MBAR_INVAL(MBK1); MBAR_INVAL(MBV);
    }
    __syncthreads();
    if (wid == 0) TCGEN05_DEALLOC(tb, 256);
#else
    // -------- fallback: fp32 flash, two 64-row halves --------
    extern __shared__ float smf[];
    float* Qs = smf;
    float* Ks = Qs + 64 * 68;
    float* Vs = Ks + 64 * 68;
    float* Ps = Vs + 64 * 64;
    float* bias_s = Ps + 64 * 64;
    const int tid = threadIdx.x;
    const int bh = blockIdx.y, h = bh & 7, bb = bh >> 3;
    const int tr = tid >> 4, tc = tid & 15;
    const int r0 = tr * 4, c0 = tc * 4;

    for (int hf = 0; hf < 2; hf++) {
        const int q0 = blockIdx.x * 128 + hf * 64;
        const float* Qbase = Qg + ((size_t)bh * 2048 + q0) * 64;
        const float* Kbase = Kg + (size_t)bh * 2048 * 64;
#pragma unroll
        for (int t = 0; t < 4; t++) {
            int lin = tid + t * 256;
            int r = lin >> 4, kc2 = (lin & 15) << 2;
            float4 v = *(const float4*)(Qbase + r * 64 + kc2);
            v.x *= 0.125f; v.y *= 0.125f; v.z *= 0.125f; v.w *= 0.125f;
            *(float4*)(Qs + r * 68 + kc2) = v;
        }
        float m_i[4], l_i[4], o[4][4];
#pragma unroll
        for (int i = 0; i < 4; i++) {
            m_i[i] = -1e30f; l_i[i] = 0.f;
#pragma unroll
            for (int d = 0; d < 4; d++) o[i][d] = 0.f;
        }
        for (int t = 0; t < 32; t++) {
            const int ck0 = t * 64;
#pragma unroll
            for (int tt = 0; tt < 4; tt++) {
                int lin = tid + tt * 256;
                int r = lin >> 4, kc2 = (lin & 15) << 2;
                float4 kv = *(const float4*)(Kbase + (size_t)(ck0 + r) * 64 + kc2);
                *(float4*)(Ks + r * 68 + kc2) = kv;
            }
#pragma unroll
            for (int tt = 0; tt < 16; tt++) {
                int lin = tid + tt * 256;
                int r = lin & 63, cdk = lin >> 6;
                Vs[r * 64 + cdk] = Vtg[((size_t)bh * 64 + cdk) * 2048 + ck0 + r];
            }
            if (tid < 127)
                bias_s[tid] = rel[(size_t)(q0 - ck0 + 1984 + tid) * 8 + h];
            __syncthreads();

            float s[4][4];
#pragma unroll
            for (int i = 0; i < 4; i++)
#pragma unroll
                for (int j = 0; j < 4; j++) s[i][j] = 0.f;
#pragma unroll
            for (int k = 0; k < 64; k += 4) {
                float4 a4[4], b4[4];
#pragma unroll
                for (int i = 0; i < 4; i++) a4[i] = *(const float4*)(Qs + (r0 + i) * 68 + k);
#pragma unroll
                for (int j = 0; j < 4; j++) b4[j] = *(const float4*)(Ks + (c0 + j) * 68 + k);
#pragma unroll
                for (int i = 0; i < 4; i++)
#pragma unroll
                    for (int j = 0; j < 4; j++) {
                        s[i][j] = fmaf(a4[i].x, b4[j].x, s[i][j]);
                        s[i][j] = fmaf(a4[i].y, b4[j].y, s[i][j]);
                        s[i][j] = fmaf(a4[i].z, b4[j].z, s[i][j]);
                        s[i][j] = fmaf(a4[i].w, b4[j].w, s[i][j]);
                    }
            }
#pragma unroll
            for (int i = 0; i < 4; i++) {
                int bi = 63 + (r0 + i) - c0;
                s[i][0] += bias_s[bi];   s[i][1] += bias_s[bi - 1];
                s[i][2] += bias_s[bi - 2]; s[i][3] += bias_s[bi - 3];
                float rmax = fmaxf(fmaxf(s[i][0], s[i][1]), fmaxf(s[i][2], s[i][3]));
#pragma unroll
                for (int off = 8; off >= 1; off >>= 1)
                    rmax = fmaxf(rmax, __shfl_xor_sync(0xffffffffu, rmax, off));
                float m_new = fmaxf(m_i[i], rmax);
                float corr = __expf(m_i[i] - m_new);
                m_i[i] = m_new;
                float p0 = __expf(s[i][0] - m_new), p1 = __expf(s[i][1] - m_new);
                float p2 = __expf(s[i][2] - m_new), p3 = __expf(s[i][3] - m_new);
                float rsum = (p0 + p1) + (p2 + p3);
#pragma unroll
                for (int off = 8; off >= 1; off >>= 1)
                    rsum += __shfl_xor_sync(0xffffffffu, rsum, off);
                l_i[i] = l_i[i] * corr + rsum;
                o[i][0] *= corr; o[i][1] *= corr; o[i][2] *= corr; o[i][3] *= corr;
                *(float4*)(Ps + (r0 + i) * 64 + c0) = make_float4(p0, p1, p2, p3);
            }
            __syncthreads();
#pragma unroll
            for (int j = 0; j < 64; j += 4) {
                float4 p4[4], v4[4];
#pragma unroll
                for (int i = 0; i < 4; i++) p4[i] = *(const float4*)(Ps + (r0 + i) * 64 + j);
#pragma unroll
                for (int jj = 0; jj < 4; jj++) v4[jj] = *(const float4*)(Vs + (j + jj) * 64 + c0);
#pragma unroll
                for (int i = 0; i < 4; i++) {
                    o[i][0] = fmaf(p4[i].x, v4[0].x, o[i][0]); o[i][1] = fmaf(p4[i].x, v4[0].y, o[i][1]);
                    o[i][2] = fmaf(p4[i].x, v4[0].z, o[i][2]); o[i][3] = fmaf(p4[i].x, v4[0].w, o[i][3]);
                    o[i][0] = fmaf(p4[i].y, v4[1].x, o[i][0]); o[i][1] = fmaf(p4[i].y, v4[1].y, o[i][1]);
                    o[i][2] = fmaf(p4[i].y, v4[1].z, o[i][2]); o[i][3] = fmaf(p4[i].y, v4[1].w, o[i][3]);
                    o[i][0] = fmaf(p4[i].z, v4[2].x, o[i][0]); o[i][1] = fmaf(p4[i].z, v4[2].y, o[i][1]);
                    o[i][2] = fmaf(p4[i].z, v4[2].z, o[i][2]); o[i][3] = fmaf(p4[i].z, v4[2].w, o[i][3]);
                    o[i][0] = fmaf(p4[i].w, v4[3].x, o[i][0]); o[i][1] = fmaf(p4[i].w, v4[3].y, o[i][1]);
                    o[i][2] = fmaf(p4[i].w, v4[3].z, o[i][2]); o[i][3] = fmaf(p4[i].w, v4[3].w, o[i][3]);
                }
            }
            __syncthreads();
        }
        float* AObase = AO + ((size_t)bb * 2048 + q0) * 512 + h * 64;
#pragma unroll
        for (int i = 0; i < 4; i++) {
            float inv = 1.0f / l_i[i];
            *(float4*)(AObase + (size_t)(r0 + i) * 512 + c0) =
                make_float4(o[i][0] * inv, o[i][1] * inv, o[i][2] * inv, o[i][3] * inv);
        }
        __syncthreads();
    }
#endif
}

// ===========================================================================
extern "C" void kernel_launch(void* const* d_in, const int* in_sizes, int n_in,
                              void* d_out, int out_size)
{
    const float* x   = (const float*)d_in[0];
    const float* c   = (const float*)d_in[1];
    const float* Wq  = (const float*)d_in[2];
    const float* bq  = (const float*)d_in[3];
    const float* Wk  = (const float*)d_in[4];
    const float* bk  = (const float*)d_in[5];
    const float* Wv  = (const float*)d_in[6];
    const float* bv  = (const float*)d_in[7];
    const float* Wo  = (const float*)d_in[8];
    const float* bo  = (const float*)d_in[9];
    const float* rel = (const float*)d_in[10];
    float* out = (float*)d_out;

    float *qp, *kp, *vp, *aop;
    uint32_t *whi, *wlo, *qt, *kt, *vtt, *xt, *ct;
    cudaGetSymbolAddress((void**)&qp,  g_Q);
    cudaGetSymbolAddress((void**)&kp,  g_K);
    cudaGetSymbolAddress((void**)&vp,  g_Vt);
    cudaGetSymbolAddress((void**)&aop, g_AO);
    cudaGetSymbolAddress((void**)&whi, g_Whi);
    cudaGetSymbolAddress((void**)&wlo, g_Wlo);
    cudaGetSymbolAddress((void**)&qt,  g_Qt);
    cudaGetSymbolAddress((void**)&kt,  g_Kt);
    cudaGetSymbolAddress((void**)&vtt, g_Vtt);
    cudaGetSymbolAddress((void**)&xt,  g_Xt);
    cudaGetSymbolAddress((void**)&ct,  g_Ct);

    const int smem_gemm = 1024 + 2 * 49152;            // 99328
    const int smem_attn = 2048 + 3 * 32768;            // 100352 (fallback needs 68096)
    cudaFuncSetAttribute(gemm_qkv, cudaFuncAttributeMaxDynamicSharedMemorySize, smem_gemm);
    cudaFuncSetAttribute(gemm_o,   cudaFuncAttributeMaxDynamicSharedMemorySize, smem_gemm);
    cudaFuncSetAttribute(attn_tf32, cudaFuncAttributeMaxDynamicSharedMemorySize, smem_attn);

    presplit_w<<<dim3(128, 4), 256>>>(Wq, Wk, Wv, Wo, whi, wlo);
    preconv_a<<<dim3(2048, 2), 256>>>(x, c, xt, ct);
    gemm_qkv<<<dim3(64, 4, 3), 256, smem_gemm>>>(x, c, Wq, bq, Wk, bk, Wv, bv,
                                                 whi, wlo, xt, ct,
                                                 qp, kp, vp, qt, kt, vtt);
    attn_tf32<<<dim3(16, 32), 256, smem_attn>>>(rel, qt, kt, vtt, qp, kp, vp, aop);
    gemm_o<<<dim3(64, 4), 256, smem_gemm>>>(aop, Wo, whi, wlo, bo, out);
}

// round 15
// speedup vs baseline: 1.0367x; 1.0367x over previous
#include <cuda_runtime.h>
#include <cstdint>

#if defined(__CUDA_ARCH_FEAT_SM100_ALL) || defined(__CUDA_ARCH_FEAT_SM103_ALL) || defined(__CUDA_ARCH_FEAT_SM101_ALL) || defined(__CUDA_ARCH_SPECIFIC__)
#define HAS_TC 1
#else
#define HAS_TC 0
#endif

// fallback float scratch
__device__ float g_Q [4*8*2048*64];
__device__ float g_K [4*8*2048*64];
__device__ float g_Vt[4*8*64*2048];
// shared
__device__ float g_AO[4*2048*512];
// TC-path scratch
__device__ uint32_t g_Qt [4*8*2048*64];     // prescaled tf32*log2e (B,H,S,dk)
__device__ uint32_t g_Kt [4*8*16*8192];     // swizzled 128x64 tile blocks
__device__ uint32_t g_Vtt[4*8*16*8192];     // swizzled 64x128 tile blocks
__device__ uint32_t g_Whi[4*512*512];       // chunk-blocked pre-swizzled
__device__ uint32_t g_Wlo[4*512*512];

#if HAS_TC
__device__ __forceinline__ uint32_t elect_one_pred() {
    uint32_t p;
    asm volatile("{\n\t.reg .pred p;\n\telect.sync _|p, 0xFFFFFFFF;\n\tselp.b32 %0,1,0,p;\n\t}" : "=r"(p));
    return p;
}
__device__ __forceinline__ uint32_t smem_to_u32(const void* p) {
    uint32_t a;
    asm("{ .reg .u64 t; cvta.to.shared.u64 t, %1; cvt.u32.u64 %0, t; }" : "=r"(a) : "l"(p));
    return a;
}
#define TCGEN05_ALLOC(s, n) asm volatile("tcgen05.alloc.cta_group::1.sync.aligned.shared::cta.b32 [%0], %1;" :: "r"((uint32_t)(s)), "r"((uint32_t)(n)) : "memory")
#define TCGEN05_RELINQ() asm volatile("tcgen05.relinquish_alloc_permit.cta_group::1.sync.aligned;")
#define TCGEN05_DEALLOC(t, n) asm volatile("tcgen05.dealloc.cta_group::1.sync.aligned.b32 %0, %1;" :: "r"(t), "r"((uint32_t)(n)))
#define TCGEN05_COMMIT(m) asm volatile("tcgen05.commit.cta_group::1.mbarrier::arrive::one.shared::cluster.b64 [%0];" :: "r"((uint32_t)(m)) : "memory")
#define TCGEN05_WAIT_LD() asm volatile("tcgen05.wait::ld.sync.aligned;" ::: "memory")
#define TCGEN05_WAIT_ST() asm volatile("tcgen05.wait::st.sync.aligned;" ::: "memory")
#define TC_FENCE_BEFORE() asm volatile("tcgen05.fence::before_thread_sync;" ::: "memory")
#define TC_FENCE_AFTER()  asm volatile("tcgen05.fence::after_thread_sync;" ::: "memory")
#define FENCE_ASYNC() asm volatile("fence.proxy.async.shared::cta;" ::: "memory")
#define MBAR_INIT(m, c) asm volatile("mbarrier.init.shared.b64 [%0], %1;" :: "r"((uint32_t)(m)), "r"((uint32_t)(c)) : "memory")
#define MBAR_INVAL(m) asm volatile("mbarrier.inval.shared.b64 [%0];" :: "r"((uint32_t)(m)) : "memory")
#define MBAR_EXPECT(m, bytes) asm volatile("mbarrier.arrive.expect_tx.shared.b64 _, [%0], %1;" :: "r"((uint32_t)(m)), "r"((uint32_t)(bytes)) : "memory")
#define BULK_CP(dst, src, bytes, mbar) \
    asm volatile("cp.async.bulk.shared::cluster.global.mbarrier::complete_tx::bytes [%0], [%1], %2, [%3];" \
        :: "r"((uint32_t)(dst)), "l"(src), "r"((uint32_t)(bytes)), "r"((uint32_t)(mbar)) : "memory")
#define MBAR_WAIT(m, par) do { \
    uint32_t _m=(uint32_t)(m), _p=(uint32_t)(par), _d; \
    asm volatile("{\n\t.reg .pred p;\n\tmbarrier.try_wait.parity.acquire.cta.shared::cta.b64 p, [%1], %2;\n\tselp.b32 %0,1,0,p;\n\t}" : "=r"(_d) : "r"(_m), "r"(_p) : "memory"); \
    if (!_d) { asm volatile("{\n\t.reg .pred P1;\n\tWL_%=:\n\tmbarrier.try_wait.parity.acquire.cta.shared::cta.b64 P1, [%0], %1, 0x989680;\n\t@P1 bra.uni WD_%=;\n\tbra.uni WL_%=;\n\tWD_%=:\n\t}" :: "r"(_m), "r"(_p) : "memory"); } } while (0)

#define LDTM32(r, a) asm volatile("tcgen05.ld.sync.aligned.32x32b.x32.b32 " \
    "{%0,%1,%2,%3,%4,%5,%6,%7,%8,%9,%10,%11,%12,%13,%14,%15,%16,%17,%18,%19,%20,%21,%22,%23,%24,%25,%26,%27,%28,%29,%30,%31}, [%32];" \
    : "=r"((r)[0]),"=r"((r)[1]),"=r"((r)[2]),"=r"((r)[3]),"=r"((r)[4]),"=r"((r)[5]),"=r"((r)[6]),"=r"((r)[7]), \
      "=r"((r)[8]),"=r"((r)[9]),"=r"((r)[10]),"=r"((r)[11]),"=r"((r)[12]),"=r"((r)[13]),"=r"((r)[14]),"=r"((r)[15]), \
      "=r"((r)[16]),"=r"((r)[17]),"=r"((r)[18]),"=r"((r)[19]),"=r"((r)[20]),"=r"((r)[21]),"=r"((r)[22]),"=r"((r)[23]), \
      "=r"((r)[24]),"=r"((r)[25]),"=r"((r)[26]),"=r"((r)[27]),"=r"((r)[28]),"=r"((r)[29]),"=r"((r)[30]),"=r"((r)[31]) : "r"(a))
#define STTM32(a, r) asm volatile("tcgen05.st.sync.aligned.32x32b.x32.b32 [%0], " \
    "{%1,%2,%3,%4,%5,%6,%7,%8,%9,%10,%11,%12,%13,%14,%15,%16,%17,%18,%19,%20,%21,%22,%23,%24,%25,%26,%27,%28,%29,%30,%31,%32};" \
    :: "r"(a), "r"((r)[0]),"r"((r)[1]),"r"((r)[2]),"r"((r)[3]),"r"((r)[4]),"r"((r)[5]),"r"((r)[6]),"r"((r)[7]), \
       "r"((r)[8]),"r"((r)[9]),"r"((r)[10]),"r"((r)[11]),"r"((r)[12]),"r"((r)[13]),"r"((r)[14]),"r"((r)[15]), \
       "r"((r)[16]),"r"((r)[17]),"r"((r)[18]),"r"((r)[19]),"r"((r)[20]),"r"((r)[21]),"r"((r)[22]),"r"((r)[23]), \
       "r"((r)[24]),"r"((r)[25]),"r"((r)[26]),"r"((r)[27]),"r"((r)[28]),"r"((r)[29]),"r"((r)[30]),"r"((r)[31]) : "memory")

static constexpr uint64_t DESC_BASE =
    (uint64_t(2) << 61) | (uint64_t(1) << 46) | (uint64_t(64) << 32) | (uint64_t(1) << 16);
#define MAKE_DESC(b) (DESC_BASE | ((uint64_t)((b) >> 4) & 0x3FFF))
#define SWZ(o) ((o) ^ (((o) >> 3) & 0x70))

__device__ __forceinline__ constexpr uint32_t idesc_tf32(int M, int N) {
    return (1u << 4) | (2u << 7) | (2u << 10) | ((uint32_t)(N / 8) << 17) | ((uint32_t)(M / 16) << 24);
}
__device__ __forceinline__ void mma_ss(uint32_t d, uint64_t ad, uint64_t bd, uint32_t id, uint32_t en) {
    asm volatile("{\n\t.reg .pred p;\n\tsetp.ne.u32 p, %5, 0;\n\t"
        "tcgen05.mma.cta_group::1.kind::tf32 [%0], %1, %2, %3, {%4,%4,%4,%4}, p;\n\t}"
        :: "r"(d), "l"(ad), "l"(bd), "r"(id), "r"(0u), "r"(en) : "memory");
}
__device__ __forceinline__ void mma_ts(uint32_t d, uint32_t at, uint64_t bd, uint32_t id, uint32_t en) {
    asm volatile("{\n\t.reg .pred p;\n\tsetp.ne.u32 p, %5, 0;\n\t"
        "tcgen05.mma.cta_group::1.kind::tf32 [%0], [%1], %2, %3, {%4,%4,%4,%4}, p;\n\t}"
        :: "r"(d), "r"(at), "l"(bd), "r"(id), "r"(0u), "r"(en) : "memory");
}
__device__ __forceinline__ uint32_t f2tf32(float x) {
    uint32_t r; asm("cvt.rna.tf32.f32 %0, %1;" : "=r"(r) : "f"(x)); return r;
}
__device__ __forceinline__ void split_tf32(float x, uint32_t& hi, uint32_t& lo) {
    hi = __float_as_uint(x) & 0xFFFFE000u;
    lo = f2tf32(x - __uint_as_float(hi));
}
__device__ __forceinline__ uint32_t blk_off(int row, int col, int atom_rows) {
    return (uint32_t)((((col >> 5) * atom_rows + (row >> 3)) * 8 + (row & 7)) * 128 + ((col & 31) << 2));
}
#endif  // HAS_TC

// ---- W pre-split into chunk-blocked pre-swizzled hi/lo blocks ----
__global__ __launch_bounds__(256) void presplit_w(
    const float* __restrict__ Wq, const float* __restrict__ Wk,
    const float* __restrict__ Wv, const float* __restrict__ Wo,
    uint32_t* __restrict__ whi, uint32_t* __restrict__ wlo)
{
#if HAS_TC
    const int m = blockIdx.y;
    const float* W = (m == 0) ? Wq : (m == 1) ? Wk : (m == 2) ? Wv : Wo;
    const int row_g = blockIdx.x * 4 + (threadIdx.x >> 6);
    const int k0 = (threadIdx.x & 63) * 8;
    const int bn_tile = row_g >> 7, row = row_g & 127;
    const size_t blk_base = ((size_t)m * 4 + bn_tile) * 16;
#pragma unroll
    for (int p = 0; p < 2; p++) {
        const int k = k0 + p * 4;
        float4 v = *(const float4*)(W + (size_t)row_g * 512 + k);
        uint4 h, l;
        split_tf32(v.x, h.x, l.x); split_tf32(v.y, h.y, l.y);
        split_tf32(v.z, h.z, l.z); split_tf32(v.w, h.w, l.w);
        const int ch = k >> 5, col = k & 31;
        const uint32_t off = SWZ((uint32_t)(row * 128 + col * 4)) >> 2;
        *(uint4*)(whi + (blk_base + ch) * 4096 + off) = h;
        *(uint4*)(wlo + (blk_base + ch) * 4096 + off) = l;
    }
#endif
}

#if HAS_TC
// -------- R13 GEMM core: manual A fill + same-chunk W bulk copy --------
// MODE 0: float row-major; 5: Q tf32 prescaled(*log2e); 3: K swizzled; 4: V swizzled
__device__ __forceinline__ void gemm_core_tc(
    const float* __restrict__ A,
    const uint32_t* __restrict__ whi, const uint32_t* __restrict__ wlo,
    const float* __restrict__ bias, void* __restrict__ outv,
    int MODE, char* sm, int bm, int bn)
{
    const uint32_t sb = smem_to_u32(sm);
    const int tid = threadIdx.x, wid = tid >> 5, lid = tid & 31;
    const uint32_t MBM0 = sb + 8, MBM1 = sb + 16, MBW0 = sb + 24, MBW1 = sb + 32;
    const uint32_t ID = idesc_tf32(128, 128);

    if (wid == 0) { TCGEN05_ALLOC(sb, 128); TCGEN05_RELINQ(); }
    if (tid == 0) { MBAR_INIT(MBM0, 1); MBAR_INIT(MBM1, 1); MBAR_INIT(MBW0, 1); MBAR_INIT(MBW1, 1); }
    __syncthreads();
    uint32_t tb;
    asm volatile("ld.shared.b32 %0, [%1];" : "=r"(tb) : "r"(sb));

    const uint32_t* wbh = whi + (size_t)(bn >> 7) * 16 * 4096;
    const uint32_t* wbl = wlo + (size_t)(bn >> 7) * 16 * 4096;
    const int ar = tid >> 3, ac = (tid & 7) << 2;
    float4 a4[4];
#pragma unroll
    for (int t = 0; t < 4; t++)
        a4[t] = *(const float4*)(A + (size_t)(bm + ar + t * 32) * 512 + ac);

    for (int ch = 0; ch < 16; ch++) {
        if (ch >= 2) MBAR_WAIT((ch & 1) ? MBM1 : MBM0, ((ch - 2) >> 1) & 1);
        const uint32_t BUF = sb + 1024 + (uint32_t)(ch & 1) * 49152;
        if (tid == 0) {
            const uint32_t mw = (ch & 1) ? MBW1 : MBW0;
            MBAR_EXPECT(mw, 32768);
            BULK_CP(BUF + 16384, wbh + (size_t)ch * 4096, 16384, mw);
            BULK_CP(BUF + 32768, wbl + (size_t)ch * 4096, 16384, mw);
        }
#pragma unroll
        for (int t = 0; t < 4; t++) {
            uint32_t o = SWZ((uint32_t)((ar + t * 32) * 128 + ac * 4));
            uint4 h;
            h.x = f2tf32(a4[t].x); h.y = f2tf32(a4[t].y);
            h.z = f2tf32(a4[t].z); h.w = f2tf32(a4[t].w);
            *(uint4*)(sm + (BUF - sb) + o) = h;
        }
        FENCE_ASYNC();
        __syncthreads();
        MBAR_WAIT((ch & 1) ? MBW1 : MBW0, (ch >> 1) & 1);
        if (wid == 0 && elect_one_pred()) {
            TC_FENCE_AFTER();
            uint64_t ad = MAKE_DESC(BUF), wh = MAKE_DESC(BUF + 16384), wl = MAKE_DESC(BUF + 32768);
#pragma unroll
            for (int ks = 0; ks < 4; ks++) {
                mma_ss(tb, ad + ks * 2, wh + ks * 2, ID, (ch | ks) ? 1u : 0u);
                mma_ss(tb, ad + ks * 2, wl + ks * 2, ID, 1u);
            }
            TCGEN05_COMMIT((ch & 1) ? MBM1 : MBM0);
        }
        if (ch < 15) {
            const int k0 = (ch + 1) * 32;
#pragma unroll
            for (int t = 0; t < 4; t++)
                a4[t] = *(const float4*)(A + (size_t)(bm + ar + t * 32) * 512 + k0 + ac);
        }
    }
    MBAR_WAIT(MBM1, 1);
    TC_FENCE_AFTER();
    {
        const int m = bm + ((wid & 3) << 5) + lid;
        const int b = m >> 11, s = m & 2047;
#pragma unroll
        for (int cc = 0; cc < 2; cc++) {
            const int c0 = ((wid >> 2) << 6) + cc * 32;
            uint32_t r[32];
            LDTM32(r, tb + c0);
            TCGEN05_WAIT_LD();
            if (MODE == 0) {
                float* out = (float*)outv;
#pragma unroll
                for (int j = 0; j < 32; j += 4) {
                    const int n = bn + c0 + j;
                    float4 v;
                    v.x = __uint_as_float(r[j + 0]) + bias[n + 0];
                    v.y = __uint_as_float(r[j + 1]) + bias[n + 1];
                    v.z = __uint_as_float(r[j + 2]) + bias[n + 2];
                    v.w = __uint_as_float(r[j + 3]) + bias[n + 3];
                    *(float4*)(out + (size_t)m * 512 + n) = v;
                }
            } else if (MODE == 5) {
                uint32_t* qt = (uint32_t*)outv;
                const float qs = 0.125f * 1.44269504088896f;
#pragma unroll
                for (int j = 0; j < 32; j += 4) {
                    const int n = bn + c0 + j;
                    const int hh = n >> 6, dk = n & 63;
                    uint4 u;
                    u.x = f2tf32((__uint_as_float(r[j + 0]) + bias[n + 0]) * qs);
                    u.y = f2tf32((__uint_as_float(r[j + 1]) + bias[n + 1]) * qs);
                    u.z = f2tf32((__uint_as_float(r[j + 2]) + bias[n + 2]) * qs);
                    u.w = f2tf32((__uint_as_float(r[j + 3]) + bias[n + 3]) * qs);
                    *(uint4*)(qt + (((size_t)(b * 8 + hh) * 2048 + s) << 6) + dk) = u;
                }
            } else if (MODE == 3) {
                uint32_t* kt = (uint32_t*)outv;
                const int tile = s >> 7, rr = s & 127;
#pragma unroll
                for (int j = 0; j < 32; j += 4) {
                    const int n = bn + c0 + j;
                    const int hh = n >> 6, dk = n & 63;
                    uint4 u;
                    u.x = f2tf32(__uint_as_float(r[j + 0]) + bias[n + 0]);
                    u.y = f2tf32(__uint_as_float(r[j + 1]) + bias[n + 1]);
                    u.z = f2tf32(__uint_as_float(r[j + 2]) + bias[n + 2]);
                    u.w = f2tf32(__uint_as_float(r[j + 3]) + bias[n + 3]);
                    *(uint4*)(kt + ((size_t)((b * 8 + hh) * 16 + tile) << 13)
                                 + (SWZ(blk_off(rr, dk, 16)) >> 2)) = u;
                }
            } else {  // MODE 4: V
                uint32_t* vt = (uint32_t*)outv;
                const int tile = s >> 7, colv = s & 127;
#pragma unroll
                for (int j = 0; j < 32; j++) {
                    const int n = bn + c0 + j;
                    const int hh = n >> 6, dk = n & 63;
                    vt[((size_t)((b * 8 + hh) * 16 + tile) << 13)
                       + (SWZ(blk_off(dk, colv, 8)) >> 2)] =
                        f2tf32(__uint_as_float(r[j]) + bias[n]);
                }
            }
        }
    }
    TC_FENCE_BEFORE();
    __syncthreads();
    if (tid == 0) { MBAR_INVAL(MBM0); MBAR_INVAL(MBM1); MBAR_INVAL(MBW0); MBAR_INVAL(MBW1); }
    __syncthreads();
    if (wid == 0) TCGEN05_DEALLOC(tb, 128);
}
#endif  // HAS_TC

#if !HAS_TC
__device__ __forceinline__ void gemm_core_fb(
    const float* __restrict__ A, const float* __restrict__ W,
    const float* __restrict__ bias, float* __restrict__ out,
    int MODE, float* smf, int bm, int bn)
{
    float* As = smf;
    float* Bs = smf + 128 * 17;
    const int tid = threadIdx.x;
    const int r0 = (tid >> 4) * 8, c0 = (tid & 15) * 8;
    float acc[8][8];
#pragma unroll
    for (int i = 0; i < 8; i++)
#pragma unroll
        for (int j = 0; j < 8; j++) acc[i][j] = 0.f;
    for (int k0 = 0; k0 < 512; k0 += 16) {
#pragma unroll
        for (int t = 0; t < 8; t++) {
            int lin = tid + t * 256;
            int r = lin >> 4, k = lin & 15;
            As[r * 17 + k] = A[(size_t)(bm + r) * 512 + k0 + k];
            Bs[r * 17 + k] = W[(size_t)(bn + r) * 512 + k0 + k];
        }
        __syncthreads();
#pragma unroll
        for (int k = 0; k < 16; k++) {
            float a8[8], b8[8];
#pragma unroll
            for (int i = 0; i < 8; i++) a8[i] = As[(r0 + i) * 17 + k];
#pragma unroll
            for (int j = 0; j < 8; j++) b8[j] = Bs[(c0 + j) * 17 + k];
#pragma unroll
            for (int i = 0; i < 8; i++)
#pragma unroll
                for (int j = 0; j < 8; j++) acc[i][j] = fmaf(a8[i], b8[j], acc[i][j]);
        }
        __syncthreads();
    }
#pragma unroll
    for (int i = 0; i < 8; i++) {
        int m = bm + r0 + i;
#pragma unroll
        for (int j = 0; j < 8; j++) {
            int n = bn + c0 + j;
            float v = acc[i][j] + bias[n];
            if (MODE == 0) out[(size_t)m * 512 + n] = v;
            else {
                int b = m >> 11, s = m & 2047, h = n >> 6, dk = n & 63;
                if (MODE == 1) out[(((size_t)(b * 8 + h) * 2048 + s) << 6) + dk] = v;
                else           out[((size_t)(b * 8 + h) * 64 + dk) * 2048 + s] = v;
            }
        }
    }
}
#endif

__global__ __launch_bounds__(256) void gemm_qkv(
    const float* __restrict__ x, const float* __restrict__ c,
    const float* __restrict__ Wq, const float* __restrict__ bq,
    const float* __restrict__ Wk, const float* __restrict__ bk,
    const float* __restrict__ Wv, const float* __restrict__ bv,
    const uint32_t* __restrict__ whi, const uint32_t* __restrict__ wlo,
    float* __restrict__ qp, float* __restrict__ kp, float* __restrict__ vp,
    uint32_t* __restrict__ qt, uint32_t* __restrict__ kt, uint32_t* __restrict__ vtt)
{
    const int z = blockIdx.z;
    const float* A = (z == 0) ? x : c;
    const float* bias = (z == 0) ? bq : (z == 1) ? bk : bv;
#if HAS_TC
    void* out = (z == 0) ? (void*)qt : (z == 1) ? (void*)kt : (void*)vtt;
    const int MODE = (z == 0) ? 5 : (z == 1) ? 3 : 4;
    extern __shared__ char sm[];
    gemm_core_tc(A, whi + (size_t)z * 262144, wlo + (size_t)z * 262144,
                 bias, out, MODE, sm, blockIdx.x * 128, blockIdx.y * 128);
#else
    const float* W = (z == 0) ? Wq : (z == 1) ? Wk : Wv;
    float* out = (z == 0) ? qp : (z == 1) ? kp : vp;
    const int MODE = (z == 2) ? 2 : 1;
    extern __shared__ float smf[];
    gemm_core_fb(A, W, bias, out, MODE, smf, blockIdx.x * 128, blockIdx.y * 128);
#endif
}

__global__ __launch_bounds__(256) void gemm_o(
    const float* __restrict__ A, const float* __restrict__ W,
    const uint32_t* __restrict__ whi, const uint32_t* __restrict__ wlo,
    const float* __restrict__ bias, float* __restrict__ out)
{
#if HAS_TC
    extern __shared__ char sm[];
    gemm_core_tc(A, whi + (size_t)3 * 262144, wlo + (size_t)3 * 262144,
                 bias, out, 0, sm, blockIdx.x * 128, blockIdx.y * 128);
#else
    extern __shared__ float smf[];
    gemm_core_fb(A, W, bias, out, 0, smf, blockIdx.x * 128, blockIdx.y * 128);
#endif
}

// ===================== attention (R14 version: split-S + exp2, 117us measured) =====================
// TMEM (256): Q 0-63 | S/P in-place 64-191 | O 192-255
__global__ __launch_bounds__(256, 2) void attn_tf32(
    const float* __restrict__ rel,
    const uint32_t* __restrict__ qt, const uint32_t* __restrict__ kt,
    const uint32_t* __restrict__ vtt,
    const float* __restrict__ Qg, const float* __restrict__ Kg,
    const float* __restrict__ Vtg, float* __restrict__ AO)
{
#if HAS_TC
    extern __shared__ char sm[];
    const uint32_t sb = smem_to_u32(sm);
    const int tid = threadIdx.x, wid = tid >> 5, lid = tid & 31;
    const int lg = wid & 3, half = wid >> 2;
    const int q0 = blockIdx.x * 128, bh = blockIdx.y, h = bh & 7;
    const uint32_t MBS0 = sb + 8, MBS1 = sb + 16, MBPV = sb + 24;
    const uint32_t MBK0 = sb + 32, MBK1 = sb + 40, MBV = sb + 48;
    float* bias_f = (float*)(sm + 64);
    const uint32_t KB0 = sb + 2048, KB1 = KB0 + 32768, VB = KB1 + 32768;
    const uint32_t ID_S64 = idesc_tf32(128, 64), ID_PV = idesc_tf32(128, 64);
    const int QB = 0, SPB = 64, OB = 192;

    if (wid == 0) { TCGEN05_ALLOC(sb, 256); TCGEN05_RELINQ(); }
    if (tid == 0) {
        MBAR_INIT(MBS0, 1); MBAR_INIT(MBS1, 1); MBAR_INIT(MBPV, 1);
        MBAR_INIT(MBK0, 1); MBAR_INIT(MBK1, 1); MBAR_INIT(MBV, 1);
    }
    __syncthreads();
    uint32_t tb;
    asm volatile("ld.shared.b32 %0, [%1];" : "=r"(tb) : "r"(sb));

    const uint32_t* ktb = kt + ((size_t)bh * 16 << 13);
    const uint32_t* vtb = vtt + ((size_t)bh * 16 << 13);

    if (tid == 0) {
        MBAR_EXPECT(MBK0, 32768);
        BULK_CP(KB0, ktb, 32768, MBK0);
        MBAR_EXPECT(MBV, 32768);
        BULK_CP(VB, vtb, 32768, MBV);
    }
    if (tid < 128) {                                  // Q -> TMEM (prescaled, log2e folded)
        const uint32_t* qrow = qt + (((size_t)bh * 2048 + q0 + tid) << 6);
        uint32_t qh[32];
#pragma unroll
        for (int p = 0; p < 2; p++) {
#pragma unroll
            for (int j4 = 0; j4 < 8; j4++)
                *(uint4*)(qh + j4 * 4) = *(const uint4*)(qrow + p * 32 + j4 * 4);
            STTM32(tb + QB + p * 32 + ((uint32_t)(tid >> 5) << 21), qh);
        }
        TCGEN05_WAIT_ST();
    }
    TC_FENCE_BEFORE();
    __syncthreads();

    float l_acc = 0.f;
    const int qr = lg * 32 + lid;

    for (int t = 0; t < 16; t++) {
        for (int u = tid; u < 255; u += 256)
            bias_f[u] = rel[(size_t)(q0 - t * 128 + 1920 + u) * 8 + h] * 1.44269504088896f;

        MBAR_WAIT((t & 1) ? MBK1 : MBK0, (t >> 1) & 1);
        if (wid == 0 && elect_one_pred()) {           // split S: two N=64 halves
            TC_FENCE_AFTER();
            uint64_t kd = MAKE_DESC((t & 1) ? KB1 : KB0);
#pragma unroll
            for (int ks = 0; ks < 8; ks++) {
                uint64_t ko = (uint64_t)((ks >> 2) * 1024 + (ks & 3) * 2);
                mma_ts(tb + SPB, tb + QB + ks * 8, kd + ko, ID_S64, ks ? 1u : 0u);
            }
            TCGEN05_COMMIT(MBS0);
#pragma unroll
            for (int ks = 0; ks < 8; ks++) {
                uint64_t ko = (uint64_t)((ks >> 2) * 1024 + (ks & 3) * 2);
                mma_ts(tb + SPB + 64, tb + QB + ks * 8, kd + 512 + ko, ID_S64, ks ? 1u : 0u);
            }
            TCGEN05_COMMIT(MBS1);
        }
        if (tid == 0 && t < 15) {
            const uint32_t KBn = ((t + 1) & 1) ? KB1 : KB0;
            MBAR_EXPECT(((t + 1) & 1) ? MBK1 : MBK0, 32768);
            BULK_CP(KBn, ktb + ((size_t)(t + 1) << 13), 32768, ((t + 1) & 1) ? MBK1 : MBK0);
        }
        if (t > 0) {
            MBAR_WAIT(MBPV, (t - 1) & 1);
            if (tid == 0) {
                MBAR_EXPECT(MBV, 32768);
                BULK_CP(VB, vtb + ((size_t)t << 13), 32768, MBV);
            }
        }
        __syncthreads();

        MBAR_WAIT(half ? MBS1 : MBS0, t & 1);
        TC_FENCE_AFTER();
#pragma unroll
        for (int cc = 0; cc < 2; cc++) {
            const int c = half * 2 + cc;
            uint32_t r[32];
            LDTM32(r, tb + SPB + 32 * c);
            TCGEN05_WAIT_LD();
            uint32_t pr[32];
#pragma unroll
            for (int j = 0; j < 32; j++) {
                float s = __uint_as_float(r[j]) + bias_f[qr - (32 * c + j) + 127];
                float p = exp2f(s);
                l_acc += p;
                pr[j] = f2tf32(p);
            }
            STTM32(tb + SPB + 32 * c + ((uint32_t)lg << 21), pr);
        }
        TCGEN05_WAIT_ST();
        TC_FENCE_BEFORE();
        __syncthreads();

        MBAR_WAIT(MBV, t & 1);
        if (wid == 0 && elect_one_pred()) {
            TC_FENCE_AFTER();
            uint64_t vd = MAKE_DESC(VB);
#pragma unroll
            for (int ks = 0; ks < 16; ks++) {
                uint64_t vo = (uint64_t)((ks >> 2) * 512 + (ks & 3) * 2);
                mma_ts(tb + OB, tb + SPB + ks * 8, vd + vo, ID_PV, (t == 0 && ks == 0) ? 0u : 1u);
            }
            TCGEN05_COMMIT(MBPV);
        }
    }
    MBAR_WAIT(MBPV, 1);

    __syncthreads();
    float* l_sh = (float*)(sm + 64);
    l_sh[tid] = l_acc;
    __syncthreads();
    const float inv = 1.0f / (l_sh[tid & 127] + l_sh[(tid & 127) + 128]);

    TC_FENCE_AFTER();
    {
        uint32_t r[32];
        LDTM32(r, tb + OB + 32 * half);
        TCGEN05_WAIT_LD();
        const int b = bh >> 3;
        float* dst = AO + ((size_t)b * 2048 + q0 + qr) * 512 + h * 64 + 32 * half;
#pragma unroll
        for (int j = 0; j < 32; j++) dst[j] = __uint_as_float(r[j]) * inv;
    }
    TC_FENCE_BEFORE();
    __syncthreads();
    if (tid == 0) {
        MBAR_INVAL(MBS0); MBAR_INVAL(MBS1); MBAR_INVAL(MBPV);
        MBAR_INVAL(MBK0); MBAR_INVAL(MBK1); MBAR_INVAL(MBV);
    }
    __syncthreads();
    if (wid == 0) TCGEN05_DEALLOC(tb, 256);
#else
    // -------- fallback: fp32 flash, two 64-row halves --------
    extern __shared__ float smf[];
    float* Qs = smf;
    float* Ks = Qs + 64 * 68;
    float* Vs = Ks + 64 * 68;
    float* Ps = Vs + 64 * 64;
    float* bias_s = Ps + 64 * 64;
    const int tid = threadIdx.x;
    const int bh = blockIdx.y, h = bh & 7, bb = bh >> 3;
    const int tr = tid >> 4, tc = tid & 15;
    const int r0 = tr * 4, c0 = tc * 4;

    for (int hf = 0; hf < 2; hf++) {
        const int q0 = blockIdx.x * 128 + hf * 64;
        const float* Qbase = Qg + ((size_t)bh * 2048 + q0) * 64;
        const float* Kbase = Kg + (size_t)bh * 2048 * 64;
#pragma unroll
        for (int t = 0; t < 4; t++) {
            int lin = tid + t * 256;
            int r = lin >> 4, kc2 = (lin & 15) << 2;
            float4 v = *(const float4*)(Qbase + r * 64 + kc2);
            v.x *= 0.125f; v.y *= 0.125f; v.z *= 0.125f; v.w *= 0.125f;
            *(float4*)(Qs + r * 68 + kc2) = v;
        }
        float m_i[4], l_i[4], o[4][4];
#pragma unroll
        for (int i = 0; i < 4; i++) {
            m_i[i] = -1e30f; l_i[i] = 0.f;
#pragma unroll
            for (int d = 0; d < 4; d++) o[i][d] = 0.f;
        }
        for (int t = 0; t < 32; t++) {
            const int ck0 = t * 64;
#pragma unroll
            for (int tt = 0; tt < 4; tt++) {
                int lin = tid + tt * 256;
                int r = lin >> 4, kc2 = (lin & 15) << 2;
                float4 kv = *(const float4*)(Kbase + (size_t)(ck0 + r) * 64 + kc2);
                *(float4*)(Ks + r * 68 + kc2) = kv;
            }
#pragma unroll
            for (int tt = 0; tt < 16; tt++) {
                int lin = tid + tt * 256;
                int r = lin & 63, cdk = lin >> 6;
                Vs[r * 64 + cdk] = Vtg[((size_t)bh * 64 + cdk) * 2048 + ck0 + r];
            }
            if (tid < 127)
                bias_s[tid] = rel[(size_t)(q0 - ck0 + 1984 + tid) * 8 + h];
            __syncthreads();

            float s[4][4];
#pragma unroll
            for (int i = 0; i < 4; i++)
#pragma unroll
                for (int j = 0; j < 4; j++) s[i][j] = 0.f;
#pragma unroll
            for (int k = 0; k < 64; k += 4) {
                float4 a4[4], b4[4];
#pragma unroll
                for (int i = 0; i < 4; i++) a4[i] = *(const float4*)(Qs + (r0 + i) * 68 + k);
#pragma unroll
                for (int j = 0; j < 4; j++) b4[j] = *(const float4*)(Ks + (c0 + j) * 68 + k);
#pragma unroll
                for (int i = 0; i < 4; i++)
#pragma unroll
                    for (int j = 0; j < 4; j++) {
                        s[i][j] = fmaf(a4[i].x, b4[j].x, s[i][j]);
                        s[i][j] = fmaf(a4[i].y, b4[j].y, s[i][j]);
                        s[i][j] = fmaf(a4[i].z, b4[j].z, s[i][j]);
                        s[i][j] = fmaf(a4[i].w, b4[j].w, s[i][j]);
                    }
            }
#pragma unroll
            for (int i = 0; i < 4; i++) {
                int bi = 63 + (r0 + i) - c0;
                s[i][0] += bias_s[bi];   s[i][1] += bias_s[bi - 1];
                s[i][2] += bias_s[bi - 2]; s[i][3] += bias_s[bi - 3];
                float rmax = fmaxf(fmaxf(s[i][0], s[i][1]), fmaxf(s[i][2], s[i][3]));
#pragma unroll
                for (int off = 8; off >= 1; off >>= 1)
                    rmax = fmaxf(rmax, __shfl_xor_sync(0xffffffffu, rmax, off));
                float m_new = fmaxf(m_i[i], rmax);
                float corr = __expf(m_i[i] - m_new);
                m_i[i] = m_new;
                float p0 = __expf(s[i][0] - m_new), p1 = __expf(s[i][1] - m_new);
                float p2 = __expf(s[i][2] - m_new), p3 = __expf(s[i][3] - m_new);
                float rsum = (p0 + p1) + (p2 + p3);
#pragma unroll
                for (int off = 8; off >= 1; off >>= 1)
                    rsum += __shfl_xor_sync(0xffffffffu, rsum, off);
                l_i[i] = l_i[i] * corr + rsum;
                o[i][0] *= corr; o[i][1] *= corr; o[i][2] *= corr; o[i][3] *= corr;
                *(float4*)(Ps + (r0 + i) * 64 + c0) = make_float4(p0, p1, p2, p3);
            }
            __syncthreads();
#pragma unroll
            for (int j = 0; j < 64; j += 4) {
                float4 p4[4], v4[4];
#pragma unroll
                for (int i = 0; i < 4; i++) p4[i] = *(const float4*)(Ps + (r0 + i) * 64 + j);
#pragma unroll
                for (int jj = 0; jj < 4; jj++) v4[jj] = *(const float4*)(Vs + (j + jj) * 64 + c0);
#pragma unroll
                for (int i = 0; i < 4; i++) {
                    o[i][0] = fmaf(p4[i].x, v4[0].x, o[i][0]); o[i][1] = fmaf(p4[i].x, v4[0].y, o[i][1]);
                    o[i][2] = fmaf(p4[i].x, v4[0].z, o[i][2]); o[i][3] = fmaf(p4[i].x, v4[0].w, o[i][3]);
                    o[i][0] = fmaf(p4[i].y, v4[1].x, o[i][0]); o[i][1] = fmaf(p4[i].y, v4[1].y, o[i][1]);
                    o[i][2] = fmaf(p4[i].y, v4[1].z, o[i][2]); o[i][3] = fmaf(p4[i].y, v4[1].w, o[i][3]);
                    o[i][0] = fmaf(p4[i].z, v4[2].x, o[i][0]); o[i][1] = fmaf(p4[i].z, v4[2].y, o[i][1]);
                    o[i][2] = fmaf(p4[i].z, v4[2].z, o[i][2]); o[i][3] = fmaf(p4[i].z, v4[2].w, o[i][3]);
                    o[i][0] = fmaf(p4[i].w, v4[3].x, o[i][0]); o[i][1] = fmaf(p4[i].w, v4[3].y, o[i][1]);
                    o[i][2] = fmaf(p4[i].w, v4[3].z, o[i][2]); o[i][3] = fmaf(p4[i].w, v4[3].w, o[i][3]);
                }
            }
            __syncthreads();
        }
        float* AObase = AO + ((size_t)bb * 2048 + q0) * 512 + h * 64;
#pragma unroll
        for (int i = 0; i < 4; i++) {
            float inv = 1.0f / l_i[i];
            *(float4*)(AObase + (size_t)(r0 + i) * 512 + c0) =
                make_float4(o[i][0] * inv, o[i][1] * inv, o[i][2] * inv, o[i][3] * inv);
        }
        __syncthreads();
    }
#endif
}

// ===========================================================================
extern "C" void kernel_launch(void* const* d_in, const int* in_sizes, int n_in,
                              void* d_out, int out_size)
{
    const float* x   = (const float*)d_in[0];
    const float* c   = (const float*)d_in[1];
    const float* Wq  = (const float*)d_in[2];
    const float* bq  = (const float*)d_in[3];
    const float* Wk  = (const float*)d_in[4];
    const float* bk  = (const float*)d_in[5];
    const float* Wv  = (const float*)d_in[6];
    const float* bv  = (const float*)d_in[7];
    const float* Wo  = (const float*)d_in[8];
    const float* bo  = (const float*)d_in[9];
    const float* rel = (const float*)d_in[10];
    float* out = (float*)d_out;

    float *qp, *kp, *vp, *aop;
    uint32_t *whi, *wlo, *qt, *kt, *vtt;
    cudaGetSymbolAddress((void**)&qp,  g_Q);
    cudaGetSymbolAddress((void**)&kp,  g_K);
    cudaGetSymbolAddress((void**)&vp,  g_Vt);
    cudaGetSymbolAddress((void**)&aop, g_AO);
    cudaGetSymbolAddress((void**)&whi, g_Whi);
    cudaGetSymbolAddress((void**)&wlo, g_Wlo);
    cudaGetSymbolAddress((void**)&qt,  g_Qt);
    cudaGetSymbolAddress((void**)&kt,  g_Kt);
    cudaGetSymbolAddress((void**)&vtt, g_Vtt);

    const int smem_gemm = 1024 + 2 * 49152;            // 99328
    const int smem_attn = 2048 + 3 * 32768;            // 100352 (fallback needs 68096)
    cudaFuncSetAttribute(gemm_qkv, cudaFuncAttributeMaxDynamicSharedMemorySize, smem_gemm);
    cudaFuncSetAttribute(gemm_o,   cudaFuncAttributeMaxDynamicSharedMemorySize, smem_gemm);
    cudaFuncSetAttribute(attn_tf32, cudaFuncAttributeMaxDynamicSharedMemorySize, smem_attn);

    presplit_w<<<dim3(128, 4), 256>>>(Wq, Wk, Wv, Wo, whi, wlo);
    gemm_qkv<<<dim3(64, 4, 3), 256, smem_gemm>>>(x, c, Wq, bq, Wk, bk, Wv, bv,
                                                 whi, wlo, qp, kp, vp, qt, kt, vtt);
    attn_tf32<<<dim3(16, 32), 256, smem_attn>>>(rel, qt, kt, vtt, qp, kp, vp, aop);
    gemm_o<<<dim3(64, 4), 256, smem_gemm>>>(aop, Wo, whi, wlo, bo, out);
}

// round 16
// speedup vs baseline: 1.0636x; 1.0259x over previous
#include <cuda_runtime.h>
#include <cstdint>

#if defined(__CUDA_ARCH_FEAT_SM100_ALL) || defined(__CUDA_ARCH_FEAT_SM103_ALL) || defined(__CUDA_ARCH_FEAT_SM101_ALL) || defined(__CUDA_ARCH_SPECIFIC__)
#define HAS_TC 1
#else
#define HAS_TC 0
#endif

// fallback float scratch
__device__ float g_Q [4*8*2048*64];
__device__ float g_K [4*8*2048*64];
__device__ float g_Vt[4*8*64*2048];
// shared
__device__ float g_AO[4*2048*512];
// TC-path scratch
__device__ uint32_t g_Qt [4*8*2048*64];     // prescaled tf32*log2e (B,H,S,dk)
__device__ uint32_t g_Kt [4*8*16*8192];     // swizzled 128x64 tile blocks
__device__ uint32_t g_Vtt[4*8*16*8192];     // swizzled 64x128 tile blocks
__device__ uint32_t g_Whi[4*512*512];       // chunk-blocked pre-swizzled
__device__ uint32_t g_Wlo[4*512*512];

#if HAS_TC
__device__ __forceinline__ uint32_t elect_one_pred() {
    uint32_t p;
    asm volatile("{\n\t.reg .pred p;\n\telect.sync _|p, 0xFFFFFFFF;\n\tselp.b32 %0,1,0,p;\n\t}" : "=r"(p));
    return p;
}
__device__ __forceinline__ uint32_t smem_to_u32(const void* p) {
    uint32_t a;
    asm("{ .reg .u64 t; cvta.to.shared.u64 t, %1; cvt.u32.u64 %0, t; }" : "=r"(a) : "l"(p));
    return a;
}
#define TCGEN05_ALLOC(s, n) asm volatile("tcgen05.alloc.cta_group::1.sync.aligned.shared::cta.b32 [%0], %1;" :: "r"((uint32_t)(s)), "r"((uint32_t)(n)) : "memory")
#define TCGEN05_RELINQ() asm volatile("tcgen05.relinquish_alloc_permit.cta_group::1.sync.aligned;")
#define TCGEN05_DEALLOC(t, n) asm volatile("tcgen05.dealloc.cta_group::1.sync.aligned.b32 %0, %1;" :: "r"(t), "r"((uint32_t)(n)))
#define TCGEN05_COMMIT(m) asm volatile("tcgen05.commit.cta_group::1.mbarrier::arrive::one.shared::cluster.b64 [%0];" :: "r"((uint32_t)(m)) : "memory")
#define TCGEN05_WAIT_LD() asm volatile("tcgen05.wait::ld.sync.aligned;" ::: "memory")
#define TCGEN05_WAIT_ST() asm volatile("tcgen05.wait::st.sync.aligned;" ::: "memory")
#define TC_FENCE_BEFORE() asm volatile("tcgen05.fence::before_thread_sync;" ::: "memory")
#define TC_FENCE_AFTER()  asm volatile("tcgen05.fence::after_thread_sync;" ::: "memory")
#define FENCE_ASYNC() asm volatile("fence.proxy.async.shared::cta;" ::: "memory")
#define MBAR_INIT(m, c) asm volatile("mbarrier.init.shared.b64 [%0], %1;" :: "r"((uint32_t)(m)), "r"((uint32_t)(c)) : "memory")
#define MBAR_INVAL(m) asm volatile("mbarrier.inval.shared.b64 [%0];" :: "r"((uint32_t)(m)) : "memory")
#define MBAR_EXPECT(m, bytes) asm volatile("mbarrier.arrive.expect_tx.shared.b64 _, [%0], %1;" :: "r"((uint32_t)(m)), "r"((uint32_t)(bytes)) : "memory")
#define BULK_CP(dst, src, bytes, mbar) \
    asm volatile("cp.async.bulk.shared::cluster.global.mbarrier::complete_tx::bytes [%0], [%1], %2, [%3];" \
        :: "r"((uint32_t)(dst)), "l"(src), "r"((uint32_t)(bytes)), "r"((uint32_t)(mbar)) : "memory")
#define MBAR_WAIT(m, par) do { \
    uint32_t _m=(uint32_t)(m), _p=(uint32_t)(par), _d; \
    asm volatile("{\n\t.reg .pred p;\n\tmbarrier.try_wait.parity.acquire.cta.shared::cta.b64 p, [%1], %2;\n\tselp.b32 %0,1,0,p;\n\t}" : "=r"(_d) : "r"(_m), "r"(_p) : "memory"); \
    if (!_d) { asm volatile("{\n\t.reg .pred P1;\n\tWL_%=:\n\tmbarrier.try_wait.parity.acquire.cta.shared::cta.b64 P1, [%0], %1, 0x989680;\n\t@P1 bra.uni WD_%=;\n\tbra.uni WL_%=;\n\tWD_%=:\n\t}" :: "r"(_m), "r"(_p) : "memory"); } } while (0)

#define LDTM32(r, a) asm volatile("tcgen05.ld.sync.aligned.32x32b.x32.b32 " \
    "{%0,%1,%2,%3,%4,%5,%6,%7,%8,%9,%10,%11,%12,%13,%14,%15,%16,%17,%18,%19,%20,%21,%22,%23,%24,%25,%26,%27,%28,%29,%30,%31}, [%32];" \
    : "=r"((r)[0]),"=r"((r)[1]),"=r"((r)[2]),"=r"((r)[3]),"=r"((r)[4]),"=r"((r)[5]),"=r"((r)[6]),"=r"((r)[7]), \
      "=r"((r)[8]),"=r"((r)[9]),"=r"((r)[10]),"=r"((r)[11]),"=r"((r)[12]),"=r"((r)[13]),"=r"((r)[14]),"=r"((r)[15]), \
      "=r"((r)[16]),"=r"((r)[17]),"=r"((r)[18]),"=r"((r)[19]),"=r"((r)[20]),"=r"((r)[21]),"=r"((r)[22]),"=r"((r)[23]), \
      "=r"((r)[24]),"=r"((r)[25]),"=r"((r)[26]),"=r"((r)[27]),"=r"((r)[28]),"=r"((r)[29]),"=r"((r)[30]),"=r"((r)[31]) : "r"(a))
#define STTM32(a, r) asm volatile("tcgen05.st.sync.aligned.32x32b.x32.b32 [%0], " \
    "{%1,%2,%3,%4,%5,%6,%7,%8,%9,%10,%11,%12,%13,%14,%15,%16,%17,%18,%19,%20,%21,%22,%23,%24,%25,%26,%27,%28,%29,%30,%31,%32};" \
    :: "r"(a), "r"((r)[0]),"r"((r)[1]),"r"((r)[2]),"r"((r)[3]),"r"((r)[4]),"r"((r)[5]),"r"((r)[6]),"r"((r)[7]), \
       "r"((r)[8]),"r"((r)[9]),"r"((r)[10]),"r"((r)[11]),"r"((r)[12]),"r"((r)[13]),"r"((r)[14]),"r"((r)[15]), \
       "r"((r)[16]),"r"((r)[17]),"r"((r)[18]),"r"((r)[19]),"r"((r)[20]),"r"((r)[21]),"r"((r)[22]),"r"((r)[23]), \
       "r"((r)[24]),"r"((r)[25]),"r"((r)[26]),"r"((r)[27]),"r"((r)[28]),"r"((r)[29]),"r"((r)[30]),"r"((r)[31]) : "memory")

static constexpr uint64_t DESC_BASE =
    (uint64_t(2) << 61) | (uint64_t(1) << 46) | (uint64_t(64) << 32) | (uint64_t(1) << 16);
#define MAKE_DESC(b) (DESC_BASE | ((uint64_t)((b) >> 4) & 0x3FFF))
#define SWZ(o) ((o) ^ (((o) >> 3) & 0x70))

__device__ __forceinline__ constexpr uint32_t idesc_tf32(int M, int N) {
    return (1u << 4) | (2u << 7) | (2u << 10) | ((uint32_t)(N / 8) << 17) | ((uint32_t)(M / 16) << 24);
}
__device__ __forceinline__ void mma_ss(uint32_t d, uint64_t ad, uint64_t bd, uint32_t id, uint32_t en) {
    asm volatile("{\n\t.reg .pred p;\n\tsetp.ne.u32 p, %5, 0;\n\t"
        "tcgen05.mma.cta_group::1.kind::tf32 [%0], %1, %2, %3, {%4,%4,%4,%4}, p;\n\t}"
        :: "r"(d), "l"(ad), "l"(bd), "r"(id), "r"(0u), "r"(en) : "memory");
}
__device__ __forceinline__ void mma_ts(uint32_t d, uint32_t at, uint64_t bd, uint32_t id, uint32_t en) {
    asm volatile("{\n\t.reg .pred p;\n\tsetp.ne.u32 p, %5, 0;\n\t"
        "tcgen05.mma.cta_group::1.kind::tf32 [%0], [%1], %2, %3, {%4,%4,%4,%4}, p;\n\t}"
        :: "r"(d), "r"(at), "l"(bd), "r"(id), "r"(0u), "r"(en) : "memory");
}
__device__ __forceinline__ uint32_t f2tf32(float x) {
    uint32_t r; asm("cvt.rna.tf32.f32 %0, %1;" : "=r"(r) : "f"(x)); return r;
}
__device__ __forceinline__ void split_tf32(float x, uint32_t& hi, uint32_t& lo) {
    hi = __float_as_uint(x) & 0xFFFFE000u;
    lo = f2tf32(x - __uint_as_float(hi));
}
__device__ __forceinline__ uint32_t blk_off(int row, int col, int atom_rows) {
    return (uint32_t)((((col >> 5) * atom_rows + (row >> 3)) * 8 + (row & 7)) * 128 + ((col & 31) << 2));
}
#endif  // HAS_TC

// ---- W pre-split into chunk-blocked pre-swizzled hi/lo blocks ----
__global__ __launch_bounds__(256) void presplit_w(
    const float* __restrict__ Wq, const float* __restrict__ Wk,
    const float* __restrict__ Wv, const float* __restrict__ Wo,
    uint32_t* __restrict__ whi, uint32_t* __restrict__ wlo)
{
#if HAS_TC
    const int m = blockIdx.y;
    const float* W = (m == 0) ? Wq : (m == 1) ? Wk : (m == 2) ? Wv : Wo;
    const int row_g = blockIdx.x * 4 + (threadIdx.x >> 6);
    const int k0 = (threadIdx.x & 63) * 8;
    const int bn_tile = row_g >> 7, row = row_g & 127;
    const size_t blk_base = ((size_t)m * 4 + bn_tile) * 16;
#pragma unroll
    for (int p = 0; p < 2; p++) {
        const int k = k0 + p * 4;
        float4 v = *(const float4*)(W + (size_t)row_g * 512 + k);
        uint4 h, l;
        split_tf32(v.x, h.x, l.x); split_tf32(v.y, h.y, l.y);
        split_tf32(v.z, h.z, l.z); split_tf32(v.w, h.w, l.w);
        const int ch = k >> 5, col = k & 31;
        const uint32_t off = SWZ((uint32_t)(row * 128 + col * 4)) >> 2;
        *(uint4*)(whi + (blk_base + ch) * 4096 + off) = h;
        *(uint4*)(wlo + (blk_base + ch) * 4096 + off) = l;
    }
#endif
}

#if HAS_TC
// -------- GEMM core: manual A fill + same-chunk W bulk copy; A prefetch before W wait --------
// MODE 0: float row-major; 5: Q tf32 prescaled(*log2e); 3: K swizzled; 4: V swizzled
__device__ __forceinline__ void gemm_core_tc(
    const float* __restrict__ A,
    const uint32_t* __restrict__ whi, const uint32_t* __restrict__ wlo,
    const float* __restrict__ bias, void* __restrict__ outv,
    int MODE, char* sm, int bm, int bn)
{
    const uint32_t sb = smem_to_u32(sm);
    const int tid = threadIdx.x, wid = tid >> 5, lid = tid & 31;
    const uint32_t MBM0 = sb + 8, MBM1 = sb + 16, MBW0 = sb + 24, MBW1 = sb + 32;
    const uint32_t ID = idesc_tf32(128, 128);

    if (wid == 0) { TCGEN05_ALLOC(sb, 128); TCGEN05_RELINQ(); }
    if (tid == 0) { MBAR_INIT(MBM0, 1); MBAR_INIT(MBM1, 1); MBAR_INIT(MBW0, 1); MBAR_INIT(MBW1, 1); }
    __syncthreads();
    uint32_t tb;
    asm volatile("ld.shared.b32 %0, [%1];" : "=r"(tb) : "r"(sb));

    const uint32_t* wbh = whi + (size_t)(bn >> 7) * 16 * 4096;
    const uint32_t* wbl = wlo + (size_t)(bn >> 7) * 16 * 4096;
    const int ar = tid >> 3, ac = (tid & 7) << 2;
    float4 a4[4];
#pragma unroll
    for (int t = 0; t < 4; t++)
        a4[t] = *(const float4*)(A + (size_t)(bm + ar + t * 32) * 512 + ac);

    for (int ch = 0; ch < 16; ch++) {
        if (ch >= 2) MBAR_WAIT((ch & 1) ? MBM1 : MBM0, ((ch - 2) >> 1) & 1);
        const uint32_t BUF = sb + 1024 + (uint32_t)(ch & 1) * 49152;
        if (tid == 0) {
            const uint32_t mw = (ch & 1) ? MBW1 : MBW0;
            MBAR_EXPECT(mw, 32768);
            BULK_CP(BUF + 16384, wbh + (size_t)ch * 4096, 16384, mw);
            BULK_CP(BUF + 32768, wbl + (size_t)ch * 4096, 16384, mw);
        }
#pragma unroll
        for (int t = 0; t < 4; t++) {
            uint32_t o = SWZ((uint32_t)((ar + t * 32) * 128 + ac * 4));
            uint4 h;
            h.x = f2tf32(a4[t].x); h.y = f2tf32(a4[t].y);
            h.z = f2tf32(a4[t].z); h.w = f2tf32(a4[t].w);
            *(uint4*)(sm + (BUF - sb) + o) = h;
        }
        FENCE_ASYNC();
        __syncthreads();
        // prefetch A for next chunk BEFORE the W-copy wait: LDGs overlap the spin
        if (ch < 15) {
            const int k0 = (ch + 1) * 32;
#pragma unroll
            for (int t = 0; t < 4; t++)
                a4[t] = *(const float4*)(A + (size_t)(bm + ar + t * 32) * 512 + k0 + ac);
        }
        MBAR_WAIT((ch & 1) ? MBW1 : MBW0, (ch >> 1) & 1);
        if (wid == 0 && elect_one_pred()) {
            TC_FENCE_AFTER();
            uint64_t ad = MAKE_DESC(BUF), wh = MAKE_DESC(BUF + 16384), wl = MAKE_DESC(BUF + 32768);
#pragma unroll
            for (int ks = 0; ks < 4; ks++) {
                mma_ss(tb, ad + ks * 2, wh + ks * 2, ID, (ch | ks) ? 1u : 0u);
                mma_ss(tb, ad + ks * 2, wl + ks * 2, ID, 1u);
            }
            TCGEN05_COMMIT((ch & 1) ? MBM1 : MBM0);
        }
    }
    MBAR_WAIT(MBM1, 1);
    TC_FENCE_AFTER();
    {
        const int m = bm + ((wid & 3) << 5) + lid;
        const int b = m >> 11, s = m & 2047;
#pragma unroll
        for (int cc = 0; cc < 2; cc++) {
            const int c0 = ((wid >> 2) << 6) + cc * 32;
            uint32_t r[32];
            LDTM32(r, tb + c0);
            TCGEN05_WAIT_LD();
            if (MODE == 0) {
                float* out = (float*)outv;
#pragma unroll
                for (int j = 0; j < 32; j += 4) {
                    const int n = bn + c0 + j;
                    float4 v;
                    v.x = __uint_as_float(r[j + 0]) + bias[n + 0];
                    v.y = __uint_as_float(r[j + 1]) + bias[n + 1];
                    v.z = __uint_as_float(r[j + 2]) + bias[n + 2];
                    v.w = __uint_as_float(r[j + 3]) + bias[n + 3];
                    *(float4*)(out + (size_t)m * 512 + n) = v;
                }
            } else if (MODE == 5) {
                uint32_t* qt = (uint32_t*)outv;
                const float qs = 0.125f * 1.44269504088896f;
#pragma unroll
                for (int j = 0; j < 32; j += 4) {
                    const int n = bn + c0 + j;
                    const int hh = n >> 6, dk = n & 63;
                    uint4 u;
                    u.x = f2tf32((__uint_as_float(r[j + 0]) + bias[n + 0]) * qs);
                    u.y = f2tf32((__uint_as_float(r[j + 1]) + bias[n + 1]) * qs);
                    u.z = f2tf32((__uint_as_float(r[j + 2]) + bias[n + 2]) * qs);
                    u.w = f2tf32((__uint_as_float(r[j + 3]) + bias[n + 3]) * qs);
                    *(uint4*)(qt + (((size_t)(b * 8 + hh) * 2048 + s) << 6) + dk) = u;
                }
            } else if (MODE == 3) {
                uint32_t* kt = (uint32_t*)outv;
                const int tile = s >> 7, rr = s & 127;
#pragma unroll
                for (int j = 0; j < 32; j += 4) {
                    const int n = bn + c0 + j;
                    const int hh = n >> 6, dk = n & 63;
                    uint4 u;
                    u.x = f2tf32(__uint_as_float(r[j + 0]) + bias[n + 0]);
                    u.y = f2tf32(__uint_as_float(r[j + 1]) + bias[n + 1]);
                    u.z = f2tf32(__uint_as_float(r[j + 2]) + bias[n + 2]);
                    u.w = f2tf32(__uint_as_float(r[j + 3]) + bias[n + 3]);
                    *(uint4*)(kt + ((size_t)((b * 8 + hh) * 16 + tile) << 13)
                                 + (SWZ(blk_off(rr, dk, 16)) >> 2)) = u;
                }
            } else {  // MODE 4: V
                uint32_t* vt = (uint32_t*)outv;
                const int tile = s >> 7, colv = s & 127;
#pragma unroll
                for (int j = 0; j < 32; j++) {
                    const int n = bn + c0 + j;
                    const int hh = n >> 6, dk = n & 63;
                    vt[((size_t)((b * 8 + hh) * 16 + tile) << 13)
                       + (SWZ(blk_off(dk, colv, 8)) >> 2)] =
                        f2tf32(__uint_as_float(r[j]) + bias[n]);
                }
            }
        }
    }
    TC_FENCE_BEFORE();
    __syncthreads();
    if (tid == 0) { MBAR_INVAL(MBM0); MBAR_INVAL(MBM1); MBAR_INVAL(MBW0); MBAR_INVAL(MBW1); }
    __syncthreads();
    if (wid == 0) TCGEN05_DEALLOC(tb, 128);
}
#endif  // HAS_TC

#if !HAS_TC
__device__ __forceinline__ void gemm_core_fb(
    const float* __restrict__ A, const float* __restrict__ W,
    const float* __restrict__ bias, float* __restrict__ out,
    int MODE, float* smf, int bm, int bn)
{
    float* As = smf;
    float* Bs = smf + 128 * 17;
    const int tid = threadIdx.x;
    const int r0 = (tid >> 4) * 8, c0 = (tid & 15) * 8;
    float acc[8][8];
#pragma unroll
    for (int i = 0; i < 8; i++)
#pragma unroll
        for (int j = 0; j < 8; j++) acc[i][j] = 0.f;
    for (int k0 = 0; k0 < 512; k0 += 16) {
#pragma unroll
        for (int t = 0; t < 8; t++) {
            int lin = tid + t * 256;
            int r = lin >> 4, k = lin & 15;
            As[r * 17 + k] = A[(size_t)(bm + r) * 512 + k0 + k];
            Bs[r * 17 + k] = W[(size_t)(bn + r) * 512 + k0 + k];
        }
        __syncthreads();
#pragma unroll
        for (int k = 0; k < 16; k++) {
            float a8[8], b8[8];
#pragma unroll
            for (int i = 0; i < 8; i++) a8[i] = As[(r0 + i) * 17 + k];
#pragma unroll
            for (int j = 0; j < 8; j++) b8[j] = Bs[(c0 + j) * 17 + k];
#pragma unroll
            for (int i = 0; i < 8; i++)
#pragma unroll
                for (int j = 0; j < 8; j++) acc[i][j] = fmaf(a8[i], b8[j], acc[i][j]);
        }
        __syncthreads();
    }
#pragma unroll
    for (int i = 0; i < 8; i++) {
        int m = bm + r0 + i;
#pragma unroll
        for (int j = 0; j < 8; j++) {
            int n = bn + c0 + j;
            float v = acc[i][j] + bias[n];
            if (MODE == 0) out[(size_t)m * 512 + n] = v;
            else {
                int b = m >> 11, s = m & 2047, h = n >> 6, dk = n & 63;
                if (MODE == 1) out[(((size_t)(b * 8 + h) * 2048 + s) << 6) + dk] = v;
                else           out[((size_t)(b * 8 + h) * 64 + dk) * 2048 + s] = v;
            }
        }
    }
}
#endif

__global__ __launch_bounds__(256) void gemm_qkv(
    const float* __restrict__ x, const float* __restrict__ c,
    const float* __restrict__ Wq, const float* __restrict__ bq,
    const float* __restrict__ Wk, const float* __restrict__ bk,
    const float* __restrict__ Wv, const float* __restrict__ bv,
    const uint32_t* __restrict__ whi, const uint32_t* __restrict__ wlo,
    float* __restrict__ qp, float* __restrict__ kp, float* __restrict__ vp,
    uint32_t* __restrict__ qt, uint32_t* __restrict__ kt, uint32_t* __restrict__ vtt)
{
    const int z = blockIdx.z;
    const float* A = (z == 0) ? x : c;
    const float* bias = (z == 0) ? bq : (z == 1) ? bk : bv;
#if HAS_TC
    void* out = (z == 0) ? (void*)qt : (z == 1) ? (void*)kt : (void*)vtt;
    const int MODE = (z == 0) ? 5 : (z == 1) ? 3 : 4;
    extern __shared__ char sm[];
    gemm_core_tc(A, whi + (size_t)z * 262144, wlo + (size_t)z * 262144,
                 bias, out, MODE, sm, blockIdx.x * 128, blockIdx.y * 128);
#else
    const float* W = (z == 0) ? Wq : (z == 1) ? Wk : Wv;
    float* out = (z == 0) ? qp : (z == 1) ? kp : vp;
    const int MODE = (z == 2) ? 2 : 1;
    extern __shared__ float smf[];
    gemm_core_fb(A, W, bias, out, MODE, smf, blockIdx.x * 128, blockIdx.y * 128);
#endif
}

__global__ __launch_bounds__(256) void gemm_o(
    const float* __restrict__ A, const float* __restrict__ W,
    const uint32_t* __restrict__ whi, const uint32_t* __restrict__ wlo,
    const float* __restrict__ bias, float* __restrict__ out)
{
#if HAS_TC
    extern __shared__ char sm[];
    gemm_core_tc(A, whi + (size_t)3 * 262144, wlo + (size_t)3 * 262144,
                 bias, out, 0, sm, blockIdx.x * 128, blockIdx.y * 128);
#else
    extern __shared__ float smf[];
    gemm_core_fb(A, W, bias, out, 0, smf, blockIdx.x * 128, blockIdx.y * 128);
#endif
}

// ===================== attention (split-S + exp2; best measured) =====================
// TMEM (256): Q 0-63 | S/P in-place 64-191 | O 192-255
__global__ __launch_bounds__(256, 2) void attn_tf32(
    const float* __restrict__ rel,
    const uint32_t* __restrict__ qt, const uint32_t* __restrict__ kt,
    const uint32_t* __restrict__ vtt,
    const float* __restrict__ Qg, const float* __restrict__ Kg,
    const float* __restrict__ Vtg, float* __restrict__ AO)
{
#if HAS_TC
    extern __shared__ char sm[];
    const uint32_t sb = smem_to_u32(sm);
    const int tid = threadIdx.x, wid = tid >> 5, lid = tid & 31;
    const int lg = wid & 3, half = wid >> 2;
    const int q0 = blockIdx.x * 128, bh = blockIdx.y, h = bh & 7;
    const uint32_t MBS0 = sb + 8, MBS1 = sb + 16, MBPV = sb + 24;
    const uint32_t MBK0 = sb + 32, MBK1 = sb + 40, MBV = sb + 48;
    float* bias_f = (float*)(sm + 64);
    const uint32_t KB0 = sb + 2048, KB1 = KB0 + 32768, VB = KB1 + 32768;
    const uint32_t ID_S64 = idesc_tf32(128, 64), ID_PV = idesc_tf32(128, 64);
    const int QB = 0, SPB = 64, OB = 192;

    if (wid == 0) { TCGEN05_ALLOC(sb, 256); TCGEN05_RELINQ(); }
    if (tid == 0) {
        MBAR_INIT(MBS0, 1); MBAR_INIT(MBS1, 1); MBAR_INIT(MBPV, 1);
        MBAR_INIT(MBK0, 1); MBAR_INIT(MBK1, 1); MBAR_INIT(MBV, 1);
    }
    __syncthreads();
    uint32_t tb;
    asm volatile("ld.shared.b32 %0, [%1];" : "=r"(tb) : "r"(sb));

    const uint32_t* ktb = kt + ((size_t)bh * 16 << 13);
    const uint32_t* vtb = vtt + ((size_t)bh * 16 << 13);

    if (tid == 0) {
        MBAR_EXPECT(MBK0, 32768);
        BULK_CP(KB0, ktb, 32768, MBK0);
        MBAR_EXPECT(MBV, 32768);
        BULK_CP(VB, vtb, 32768, MBV);
    }
    if (tid < 128) {                                  // Q -> TMEM (prescaled, log2e folded)
        const uint32_t* qrow = qt + (((size_t)bh * 2048 + q0 + tid) << 6);
        uint32_t qh[32];
#pragma unroll
        for (int p = 0; p < 2; p++) {
#pragma unroll
            for (int j4 = 0; j4 < 8; j4++)
                *(uint4*)(qh + j4 * 4) = *(const uint4*)(qrow + p * 32 + j4 * 4);
            STTM32(tb + QB + p * 32 + ((uint32_t)(tid >> 5) << 21), qh);
        }
        TCGEN05_WAIT_ST();
    }
    TC_FENCE_BEFORE();
    __syncthreads();

    float l_acc = 0.f;
    const int qr = lg * 32 + lid;

    for (int t = 0; t < 16; t++) {
        for (int u = tid; u < 255; u += 256)
            bias_f[u] = rel[(size_t)(q0 - t * 128 + 1920 + u) * 8 + h] * 1.44269504088896f;

        MBAR_WAIT((t & 1) ? MBK1 : MBK0, (t >> 1) & 1);
        if (wid == 0 && elect_one_pred()) {           // split S: two N=64 halves
            TC_FENCE_AFTER();
            uint64_t kd = MAKE_DESC((t & 1) ? KB1 : KB0);
#pragma unroll
            for (int ks = 0; ks < 8; ks++) {
                uint64_t ko = (uint64_t)((ks >> 2) * 1024 + (ks & 3) * 2);
                mma_ts(tb + SPB, tb + QB + ks * 8, kd + ko, ID_S64, ks ? 1u : 0u);
            }
            TCGEN05_COMMIT(MBS0);
#pragma unroll
            for (int ks = 0; ks < 8; ks++) {
                uint64_t ko = (uint64_t)((ks >> 2) * 1024 + (ks & 3) * 2);
                mma_ts(tb + SPB + 64, tb + QB + ks * 8, kd + 512 + ko, ID_S64, ks ? 1u : 0u);
            }
            TCGEN05_COMMIT(MBS1);
        }
        if (tid == 0 && t < 15) {
            const uint32_t KBn = ((t + 1) & 1) ? KB1 : KB0;
            MBAR_EXPECT(((t + 1) & 1) ? MBK1 : MBK0, 32768);
            BULK_CP(KBn, ktb + ((size_t)(t + 1) << 13), 32768, ((t + 1) & 1) ? MBK1 : MBK0);
        }
        if (t > 0) {
            MBAR_WAIT(MBPV, (t - 1) & 1);
            if (tid == 0) {
                MBAR_EXPECT(MBV, 32768);
                BULK_CP(VB, vtb + ((size_t)t << 13), 32768, MBV);
            }
        }
        __syncthreads();

        MBAR_WAIT(half ? MBS1 : MBS0, t & 1);
        TC_FENCE_AFTER();
#pragma unroll
        for (int cc = 0; cc < 2; cc++) {
            const int c = half * 2 + cc;
            uint32_t r[32];
            LDTM32(r, tb + SPB + 32 * c);
            TCGEN05_WAIT_LD();
            uint32_t pr[32];
#pragma unroll
            for (int j = 0; j < 32; j++) {
                float s = __uint_as_float(r[j]) + bias_f[qr - (32 * c + j) + 127];
                float p = exp2f(s);
                l_acc += p;
                pr[j] = f2tf32(p);
            }
            STTM32(tb + SPB + 32 * c + ((uint32_t)lg << 21), pr);
        }
        TCGEN05_WAIT_ST();
        TC_FENCE_BEFORE();
        __syncthreads();

        MBAR_WAIT(MBV, t & 1);
        if (wid == 0 && elect_one_pred()) {
            TC_FENCE_AFTER();
            uint64_t vd = MAKE_DESC(VB);
#pragma unroll
            for (int ks = 0; ks < 16; ks++) {
                uint64_t vo = (uint64_t)((ks >> 2) * 512 + (ks & 3) * 2);
                mma_ts(tb + OB, tb + SPB + ks * 8, vd + vo, ID_PV, (t == 0 && ks == 0) ? 0u : 1u);
            }
            TCGEN05_COMMIT(MBPV);
        }
    }
    MBAR_WAIT(MBPV, 1);

    __syncthreads();
    float* l_sh = (float*)(sm + 64);
    l_sh[tid] = l_acc;
    __syncthreads();
    const float inv = 1.0f / (l_sh[tid & 127] + l_sh[(tid & 127) + 128]);

    TC_FENCE_AFTER();
    {
        uint32_t r[32];
        LDTM32(r, tb + OB + 32 * half);
        TCGEN05_WAIT_LD();
        const int b = bh >> 3;
        float* dst = AO + ((size_t)b * 2048 + q0 + qr) * 512 + h * 64 + 32 * half;
#pragma unroll
        for (int j = 0; j < 32; j++) dst[j] = __uint_as_float(r[j]) * inv;
    }
    TC_FENCE_BEFORE();
    __syncthreads();
    if (tid == 0) {
        MBAR_INVAL(MBS0); MBAR_INVAL(MBS1); MBAR_INVAL(MBPV);
        MBAR_INVAL(MBK0); MBAR_INVAL(MBK1); MBAR_INVAL(MBV);
    }
    __syncthreads();
    if (wid == 0) TCGEN05_DEALLOC(tb, 256);
#else
    // -------- fallback: fp32 flash, two 64-row halves --------
    extern __shared__ float smf[];
    float* Qs = smf;
    float* Ks = Qs + 64 * 68;
    float* Vs = Ks + 64 * 68;
    float* Ps = Vs + 64 * 64;
    float* bias_s = Ps + 64 * 64;
    const int tid = threadIdx.x;
    const int bh = blockIdx.y, h = bh & 7, bb = bh >> 3;
    const int tr = tid >> 4, tc = tid & 15;
    const int r0 = tr * 4, c0 = tc * 4;

    for (int hf = 0; hf < 2; hf++) {
        const int q0 = blockIdx.x * 128 + hf * 64;
        const float* Qbase = Qg + ((size_t)bh * 2048 + q0) * 64;
        const float* Kbase = Kg + (size_t)bh * 2048 * 64;
#pragma unroll
        for (int t = 0; t < 4; t++) {
            int lin = tid + t * 256;
            int r = lin >> 4, kc2 = (lin & 15) << 2;
            float4 v = *(const float4*)(Qbase + r * 64 + kc2);
            v.x *= 0.125f; v.y *= 0.125f; v.z *= 0.125f; v.w *= 0.125f;
            *(float4*)(Qs + r * 68 + kc2) = v;
        }
        float m_i[4], l_i[4], o[4][4];
#pragma unroll
        for (int i = 0; i < 4; i++) {
            m_i[i] = -1e30f; l_i[i] = 0.f;
#pragma unroll
            for (int d = 0; d < 4; d++) o[i][d] = 0.f;
        }
        for (int t = 0; t < 32; t++) {
            const int ck0 = t * 64;
#pragma unroll
            for (int tt = 0; tt < 4; tt++) {
                int lin = tid + tt * 256;
                int r = lin >> 4, kc2 = (lin & 15) << 2;
                float4 kv = *(const float4*)(Kbase + (size_t)(ck0 + r) * 64 + kc2);
                *(float4*)(Ks + r * 68 + kc2) = kv;
            }
#pragma unroll
            for (int tt = 0; tt < 16; tt++) {
                int lin = tid + tt * 256;
                int r = lin & 63, cdk = lin >> 6;
                Vs[r * 64 + cdk] = Vtg[((size_t)bh * 64 + cdk) * 2048 + ck0 + r];
            }
            if (tid < 127)
                bias_s[tid] = rel[(size_t)(q0 - ck0 + 1984 + tid) * 8 + h];
            __syncthreads();

            float s[4][4];
#pragma unroll
            for (int i = 0; i < 4; i++)
#pragma unroll
                for (int j = 0; j < 4; j++) s[i][j] = 0.f;
#pragma unroll
            for (int k = 0; k < 64; k += 4) {
                float4 a4[4], b4[4];
#pragma unroll
                for (int i = 0; i < 4; i++) a4[i] = *(const float4*)(Qs + (r0 + i) * 68 + k);
#pragma unroll
                for (int j = 0; j < 4; j++) b4[j] = *(const float4*)(Ks + (c0 + j) * 68 + k);
#pragma unroll
                for (int i = 0; i < 4; i++)
#pragma unroll
                    for (int j = 0; j < 4; j++) {
                        s[i][j] = fmaf(a4[i].x, b4[j].x, s[i][j]);
                        s[i][j] = fmaf(a4[i].y, b4[j].y, s[i][j]);
                        s[i][j] = fmaf(a4[i].z, b4[j].z, s[i][j]);
                        s[i][j] = fmaf(a4[i].w, b4[j].w, s[i][j]);
                    }
            }
#pragma unroll
            for (int i = 0; i < 4; i++) {
                int bi = 63 + (r0 + i) - c0;
                s[i][0] += bias_s[bi];   s[i][1] += bias_s[bi - 1];
                s[i][2] += bias_s[bi - 2]; s[i][3] += bias_s[bi - 3];
                float rmax = fmaxf(fmaxf(s[i][0], s[i][1]), fmaxf(s[i][2], s[i][3]));
#pragma unroll
                for (int off = 8; off >= 1; off >>= 1)
                    rmax = fmaxf(rmax, __shfl_xor_sync(0xffffffffu, rmax, off));
                float m_new = fmaxf(m_i[i], rmax);
                float corr = __expf(m_i[i] - m_new);
                m_i[i] = m_new;
                float p0 = __expf(s[i][0] - m_new), p1 = __expf(s[i][1] - m_new);
                float p2 = __expf(s[i][2] - m_new), p3 = __expf(s[i][3] - m_new);
                float rsum = (p0 + p1) + (p2 + p3);
#pragma unroll
                for (int off = 8; off >= 1; off >>= 1)
                    rsum += __shfl_xor_sync(0xffffffffu, rsum, off);
                l_i[i] = l_i[i] * corr + rsum;
                o[i][0] *= corr; o[i][1] *= corr; o[i][2] *= corr; o[i][3] *= corr;
                *(float4*)(Ps + (r0 + i) * 64 + c0) = make_float4(p0, p1, p2, p3);
            }
            __syncthreads();
#pragma unroll
            for (int j = 0; j < 64; j += 4) {
                float4 p4[4], v4[4];
#pragma unroll
                for (int i = 0; i < 4; i++) p4[i] = *(const float4*)(Ps + (r0 + i) * 64 + j);
#pragma unroll
                for (int jj = 0; jj < 4; jj++) v4[jj] = *(const float4*)(Vs + (j + jj) * 64 + c0);
#pragma unroll
                for (int i = 0; i < 4; i++) {
                    o[i][0] = fmaf(p4[i].x, v4[0].x, o[i][0]); o[i][1] = fmaf(p4[i].x, v4[0].y, o[i][1]);
                    o[i][2] = fmaf(p4[i].x, v4[0].z, o[i][2]); o[i][3] = fmaf(p4[i].x, v4[0].w, o[i][3]);
                    o[i][0] = fmaf(p4[i].y, v4[1].x, o[i][0]); o[i][1] = fmaf(p4[i].y, v4[1].y, o[i][1]);
                    o[i][2] = fmaf(p4[i].y, v4[1].z, o[i][2]); o[i][3] = fmaf(p4[i].y, v4[1].w, o[i][3]);
                    o[i][0] = fmaf(p4[i].z, v4[2].x, o[i][0]); o[i][1] = fmaf(p4[i].z, v4[2].y, o[i][1]);
                    o[i][2] = fmaf(p4[i].z, v4[2].z, o[i][2]); o[i][3] = fmaf(p4[i].z, v4[2].w, o[i][3]);
                    o[i][0] = fmaf(p4[i].w, v4[3].x, o[i][0]); o[i][1] = fmaf(p4[i].w, v4[3].y, o[i][1]);
                    o[i][2] = fmaf(p4[i].w, v4[3].z, o[i][2]); o[i][3] = fmaf(p4[i].w, v4[3].w, o[i][3]);
                }
            }
            __syncthreads();
        }
        float* AObase = AO + ((size_t)bb * 2048 + q0) * 512 + h * 64;
#pragma unroll
        for (int i = 0; i < 4; i++) {
            float inv = 1.0f / l_i[i];
            *(float4*)(AObase + (size_t)(r0 + i) * 512 + c0) =
                make_float4(o[i][0] * inv, o[i][1] * inv, o[i][2] * inv, o[i][3] * inv);
        }
        __syncthreads();
    }
#endif
}

// ===========================================================================
extern "C" void kernel_launch(void* const* d_in, const int* in_sizes, int n_in,
                              void* d_out, int out_size)
{
    const float* x   = (const float*)d_in[0];
    const float* c   = (const float*)d_in[1];
    const float* Wq  = (const float*)d_in[2];
    const float* bq  = (const float*)d_in[3];
    const float* Wk  = (const float*)d_in[4];
    const float* bk  = (const float*)d_in[5];
    const float* Wv  = (const float*)d_in[6];
    const float* bv  = (const float*)d_in[7];
    const float* Wo  = (const float*)d_in[8];
    const float* bo  = (const float*)d_in[9];
    const float* rel = (const float*)d_in[10];
    float* out = (float*)d_out;

    float *qp, *kp, *vp, *aop;
    uint32_t *whi, *wlo, *qt, *kt, *vtt;
    cudaGetSymbolAddress((void**)&qp,  g_Q);
    cudaGetSymbolAddress((void**)&kp,  g_K);
    cudaGetSymbolAddress((void**)&vp,  g_Vt);
    cudaGetSymbolAddress((void**)&aop, g_AO);
    cudaGetSymbolAddress((void**)&whi, g_Whi);
    cudaGetSymbolAddress((void**)&wlo, g_Wlo);
    cudaGetSymbolAddress((void**)&qt,  g_Qt);
    cudaGetSymbolAddress((void**)&kt,  g_Kt);
    cudaGetSymbolAddress((void**)&vtt, g_Vtt);

    const int smem_gemm = 1024 + 2 * 49152;            // 99328
    const int smem_attn = 2048 + 3 * 32768;            // 100352 (fallback needs 68096)
    cudaFuncSetAttribute(gemm_qkv, cudaFuncAttributeMaxDynamicSharedMemorySize, smem_gemm);
    cudaFuncSetAttribute(gemm_o,   cudaFuncAttributeMaxDynamicSharedMemorySize, smem_gemm);
    cudaFuncSetAttribute(attn_tf32, cudaFuncAttributeMaxDynamicSharedMemorySize, smem_attn);

    presplit_w<<<dim3(128, 4), 256>>>(Wq, Wk, Wv, Wo, whi, wlo);
    gemm_qkv<<<dim3(64, 4, 3), 256, smem_gemm>>>(x, c, Wq, bq, Wk, bk, Wv, bv,
                                                 whi, wlo, qp, kp, vp, qt, kt, vtt);
    attn_tf32<<<dim3(16, 32), 256, smem_attn>>>(rel, qt, kt, vtt, qp, kp, vp, aop);
    gemm_o<<<dim3(64, 4), 256, smem_gemm>>>(aop, Wo, whi, wlo, bo, out);
}

// round 17
// speedup vs baseline: 1.0766x; 1.0123x over previous
#include <cuda_runtime.h>
#include <cstdint>

#if defined(__CUDA_ARCH_FEAT_SM100_ALL) || defined(__CUDA_ARCH_FEAT_SM103_ALL) || defined(__CUDA_ARCH_FEAT_SM101_ALL) || defined(__CUDA_ARCH_SPECIFIC__)
#define HAS_TC 1
#else
#define HAS_TC 0
#endif

// fallback float scratch
__device__ float g_Q [4*8*2048*64];
__device__ float g_K [4*8*2048*64];
__device__ float g_Vt[4*8*64*2048];
// shared
__device__ float g_AO[4*2048*512];
// TC-path scratch
__device__ uint32_t g_Qt [4*8*2048*64];     // prescaled tf32*log2e (B,H,S,dk)
__device__ uint32_t g_Kt [4*8*16*8192];     // swizzled 128x64 tile blocks
__device__ uint32_t g_Vtt[4*8*16*8192];     // swizzled 64x128 tile blocks
__device__ uint32_t g_Whi[4*512*512];       // chunk-blocked pre-swizzled
__device__ uint32_t g_Wlo[4*512*512];

#if HAS_TC
__device__ __forceinline__ uint32_t elect_one_pred() {
    uint32_t p;
    asm volatile("{\n\t.reg .pred p;\n\telect.sync _|p, 0xFFFFFFFF;\n\tselp.b32 %0,1,0,p;\n\t}" : "=r"(p));
    return p;
}
__device__ __forceinline__ uint32_t smem_to_u32(const void* p) {
    uint32_t a;
    asm("{ .reg .u64 t; cvta.to.shared.u64 t, %1; cvt.u32.u64 %0, t; }" : "=r"(a) : "l"(p));
    return a;
}
#define TCGEN05_ALLOC(s, n) asm volatile("tcgen05.alloc.cta_group::1.sync.aligned.shared::cta.b32 [%0], %1;" :: "r"((uint32_t)(s)), "r"((uint32_t)(n)) : "memory")
#define TCGEN05_RELINQ() asm volatile("tcgen05.relinquish_alloc_permit.cta_group::1.sync.aligned;")
#define TCGEN05_DEALLOC(t, n) asm volatile("tcgen05.dealloc.cta_group::1.sync.aligned.b32 %0, %1;" :: "r"(t), "r"((uint32_t)(n)))
#define TCGEN05_COMMIT(m) asm volatile("tcgen05.commit.cta_group::1.mbarrier::arrive::one.shared::cluster.b64 [%0];" :: "r"((uint32_t)(m)) : "memory")
#define TCGEN05_WAIT_LD() asm volatile("tcgen05.wait::ld.sync.aligned;" ::: "memory")
#define TCGEN05_WAIT_ST() asm volatile("tcgen05.wait::st.sync.aligned;" ::: "memory")
#define TC_FENCE_BEFORE() asm volatile("tcgen05.fence::before_thread_sync;" ::: "memory")
#define TC_FENCE_AFTER()  asm volatile("tcgen05.fence::after_thread_sync;" ::: "memory")
#define FENCE_ASYNC() asm volatile("fence.proxy.async.shared::cta;" ::: "memory")
#define MBAR_INIT(m, c) asm volatile("mbarrier.init.shared.b64 [%0], %1;" :: "r"((uint32_t)(m)), "r"((uint32_t)(c)) : "memory")
#define MBAR_INVAL(m) asm volatile("mbarrier.inval.shared.b64 [%0];" :: "r"((uint32_t)(m)) : "memory")
#define MBAR_EXPECT(m, bytes) asm volatile("mbarrier.arrive.expect_tx.shared.b64 _, [%0], %1;" :: "r"((uint32_t)(m)), "r"((uint32_t)(bytes)) : "memory")
#define BULK_CP(dst, src, bytes, mbar) \
    asm volatile("cp.async.bulk.shared::cluster.global.mbarrier::complete_tx::bytes [%0], [%1], %2, [%3];" \
        :: "r"((uint32_t)(dst)), "l"(src), "r"((uint32_t)(bytes)), "r"((uint32_t)(mbar)) : "memory")
#define MBAR_WAIT(m, par) do { \
    uint32_t _m=(uint32_t)(m), _p=(uint32_t)(par), _d; \
    asm volatile("{\n\t.reg .pred p;\n\tmbarrier.try_wait.parity.acquire.cta.shared::cta.b64 p, [%1], %2;\n\tselp.b32 %0,1,0,p;\n\t}" : "=r"(_d) : "r"(_m), "r"(_p) : "memory"); \
    if (!_d) { asm volatile("{\n\t.reg .pred P1;\n\tWL_%=:\n\tmbarrier.try_wait.parity.acquire.cta.shared::cta.b64 P1, [%0], %1, 0x989680;\n\t@P1 bra.uni WD_%=;\n\tbra.uni WL_%=;\n\tWD_%=:\n\t}" :: "r"(_m), "r"(_p) : "memory"); } } while (0)

#define LDTM32(r, a) asm volatile("tcgen05.ld.sync.aligned.32x32b.x32.b32 " \
    "{%0,%1,%2,%3,%4,%5,%6,%7,%8,%9,%10,%11,%12,%13,%14,%15,%16,%17,%18,%19,%20,%21,%22,%23,%24,%25,%26,%27,%28,%29,%30,%31}, [%32];" \
    : "=r"((r)[0]),"=r"((r)[1]),"=r"((r)[2]),"=r"((r)[3]),"=r"((r)[4]),"=r"((r)[5]),"=r"((r)[6]),"=r"((r)[7]), \
      "=r"((r)[8]),"=r"((r)[9]),"=r"((r)[10]),"=r"((r)[11]),"=r"((r)[12]),"=r"((r)[13]),"=r"((r)[14]),"=r"((r)[15]), \
      "=r"((r)[16]),"=r"((r)[17]),"=r"((r)[18]),"=r"((r)[19]),"=r"((r)[20]),"=r"((r)[21]),"=r"((r)[22]),"=r"((r)[23]), \
      "=r"((r)[24]),"=r"((r)[25]),"=r"((r)[26]),"=r"((r)[27]),"=r"((r)[28]),"=r"((r)[29]),"=r"((r)[30]),"=r"((r)[31]) : "r"(a))
#define STTM32(a, r) asm volatile("tcgen05.st.sync.aligned.32x32b.x32.b32 [%0], " \
    "{%1,%2,%3,%4,%5,%6,%7,%8,%9,%10,%11,%12,%13,%14,%15,%16,%17,%18,%19,%20,%21,%22,%23,%24,%25,%26,%27,%28,%29,%30,%31,%32};" \
    :: "r"(a), "r"((r)[0]),"r"((r)[1]),"r"((r)[2]),"r"((r)[3]),"r"((r)[4]),"r"((r)[5]),"r"((r)[6]),"r"((r)[7]), \
       "r"((r)[8]),"r"((r)[9]),"r"((r)[10]),"r"((r)[11]),"r"((r)[12]),"r"((r)[13]),"r"((r)[14]),"r"((r)[15]), \
       "r"((r)[16]),"r"((r)[17]),"r"((r)[18]),"r"((r)[19]),"r"((r)[20]),"r"((r)[21]),"r"((r)[22]),"r"((r)[23]), \
       "r"((r)[24]),"r"((r)[25]),"r"((r)[26]),"r"((r)[27]),"r"((r)[28]),"r"((r)[29]),"r"((r)[30]),"r"((r)[31]) : "memory")

static constexpr uint64_t DESC_BASE =
    (uint64_t(2) << 61) | (uint64_t(1) << 46) | (uint64_t(64) << 32) | (uint64_t(1) << 16);
#define MAKE_DESC(b) (DESC_BASE | ((uint64_t)((b) >> 4) & 0x3FFF))
#define SWZ(o) ((o) ^ (((o) >> 3) & 0x70))

__device__ __forceinline__ constexpr uint32_t idesc_tf32(int M, int N) {
    return (1u << 4) | (2u << 7) | (2u << 10) | ((uint32_t)(N / 8) << 17) | ((uint32_t)(M / 16) << 24);
}
__device__ __forceinline__ void mma_ss(uint32_t d, uint64_t ad, uint64_t bd, uint32_t id, uint32_t en) {
    asm volatile("{\n\t.reg .pred p;\n\tsetp.ne.u32 p, %5, 0;\n\t"
        "tcgen05.mma.cta_group::1.kind::tf32 [%0], %1, %2, %3, {%4,%4,%4,%4}, p;\n\t}"
        :: "r"(d), "l"(ad), "l"(bd), "r"(id), "r"(0u), "r"(en) : "memory");
}
__device__ __forceinline__ void mma_ts(uint32_t d, uint32_t at, uint64_t bd, uint32_t id, uint32_t en) {
    asm volatile("{\n\t.reg .pred p;\n\tsetp.ne.u32 p, %5, 0;\n\t"
        "tcgen05.mma.cta_group::1.kind::tf32 [%0], [%1], %2, %3, {%4,%4,%4,%4}, p;\n\t}"
        :: "r"(d), "r"(at), "l"(bd), "r"(id), "r"(0u), "r"(en) : "memory");
}
__device__ __forceinline__ uint32_t f2tf32(float x) {
    uint32_t r; asm("cvt.rna.tf32.f32 %0, %1;" : "=r"(r) : "f"(x)); return r;
}
__device__ __forceinline__ void split_tf32(float x, uint32_t& hi, uint32_t& lo) {
    hi = __float_as_uint(x) & 0xFFFFE000u;
    lo = f2tf32(x - __uint_as_float(hi));
}
__device__ __forceinline__ uint32_t blk_off(int row, int col, int atom_rows) {
    return (uint32_t)((((col >> 5) * atom_rows + (row >> 3)) * 8 + (row & 7)) * 128 + ((col & 31) << 2));
}
#endif  // HAS_TC

// ---- W pre-split into chunk-blocked pre-swizzled hi/lo blocks ----
__global__ __launch_bounds__(256) void presplit_w(
    const float* __restrict__ Wq, const float* __restrict__ Wk,
    const float* __restrict__ Wv, const float* __restrict__ Wo,
    uint32_t* __restrict__ whi, uint32_t* __restrict__ wlo)
{
#if HAS_TC
    const int m = blockIdx.y;
    const float* W = (m == 0) ? Wq : (m == 1) ? Wk : (m == 2) ? Wv : Wo;
    const int row_g = blockIdx.x * 4 + (threadIdx.x >> 6);
    const int k0 = (threadIdx.x & 63) * 8;
    const int bn_tile = row_g >> 7, row = row_g & 127;
    const size_t blk_base = ((size_t)m * 4 + bn_tile) * 16;
#pragma unroll
    for (int p = 0; p < 2; p++) {
        const int k = k0 + p * 4;
        float4 v = *(const float4*)(W + (size_t)row_g * 512 + k);
        uint4 h, l;
        split_tf32(v.x, h.x, l.x); split_tf32(v.y, h.y, l.y);
        split_tf32(v.z, h.z, l.z); split_tf32(v.w, h.w, l.w);
        const int ch = k >> 5, col = k & 31;
        const uint32_t off = SWZ((uint32_t)(row * 128 + col * 4)) >> 2;
        *(uint4*)(whi + (blk_base + ch) * 4096 + off) = h;
        *(uint4*)(wlo + (blk_base + ch) * 4096 + off) = l;
    }
#endif
}

#if HAS_TC
// -------- GEMM core: W bulk copies prefetched one chunk ahead --------
// MODE 0: float row-major; 5: Q tf32 prescaled(*log2e); 3: K swizzled; 4: V swizzled
__device__ __forceinline__ void gemm_core_tc(
    const float* __restrict__ A,
    const uint32_t* __restrict__ whi, const uint32_t* __restrict__ wlo,
    const float* __restrict__ bias, void* __restrict__ outv,
    int MODE, char* sm, int bm, int bn)
{
    const uint32_t sb = smem_to_u32(sm);
    const int tid = threadIdx.x, wid = tid >> 5, lid = tid & 31;
    const uint32_t MBM0 = sb + 8, MBM1 = sb + 16, MBW0 = sb + 24, MBW1 = sb + 32;
    const uint32_t ID = idesc_tf32(128, 128);

    if (wid == 0) { TCGEN05_ALLOC(sb, 128); TCGEN05_RELINQ(); }
    if (tid == 0) { MBAR_INIT(MBM0, 1); MBAR_INIT(MBM1, 1); MBAR_INIT(MBW0, 1); MBAR_INIT(MBW1, 1); }
    __syncthreads();
    uint32_t tb;
    asm volatile("ld.shared.b32 %0, [%1];" : "=r"(tb) : "r"(sb));

    const uint32_t* wbh = whi + (size_t)(bn >> 7) * 16 * 4096;
    const uint32_t* wbl = wlo + (size_t)(bn >> 7) * 16 * 4096;
    const int ar = tid >> 3, ac = (tid & 7) << 2;
    float4 a4[4];
#pragma unroll
    for (int t = 0; t < 4; t++)
        a4[t] = *(const float4*)(A + (size_t)(bm + ar + t * 32) * 512 + ac);

    // prologue: W copies for chunk 0 into buffer 0
    if (tid == 0) {
        MBAR_EXPECT(MBW0, 32768);
        BULK_CP(sb + 1024 + 16384, wbh, 16384, MBW0);
        BULK_CP(sb + 1024 + 32768, wbl, 16384, MBW0);
    }

    for (int ch = 0; ch < 16; ch++) {
        // buffer ch&1 is free: MMA(ch-2) was waited at the tail of iteration ch-1
        const uint32_t BUF = sb + 1024 + (uint32_t)(ch & 1) * 49152;
#pragma unroll
        for (int t = 0; t < 4; t++) {
            uint32_t o = SWZ((uint32_t)((ar + t * 32) * 128 + ac * 4));
            uint4 h;
            h.x = f2tf32(a4[t].x); h.y = f2tf32(a4[t].y);
            h.z = f2tf32(a4[t].z); h.w = f2tf32(a4[t].w);
            *(uint4*)(sm + (BUF - sb) + o) = h;
        }
        FENCE_ASYNC();
        __syncthreads();
        // A prefetch for ch+1 overlaps the W wait
        if (ch < 15) {
            const int k0 = (ch + 1) * 32;
#pragma unroll
            for (int t = 0; t < 4; t++)
                a4[t] = *(const float4*)(A + (size_t)(bm + ar + t * 32) * 512 + k0 + ac);
        }
        MBAR_WAIT((ch & 1) ? MBW1 : MBW0, (ch >> 1) & 1);
        if (wid == 0 && elect_one_pred()) {
            TC_FENCE_AFTER();
            uint64_t ad = MAKE_DESC(BUF), wh = MAKE_DESC(BUF + 16384), wl = MAKE_DESC(BUF + 32768);
#pragma unroll
            for (int ks = 0; ks < 4; ks++) {
                mma_ss(tb, ad + ks * 2, wh + ks * 2, ID, (ch | ks) ? 1u : 0u);
                mma_ss(tb, ad + ks * 2, wl + ks * 2, ID, 1u);
            }
            TCGEN05_COMMIT((ch & 1) ? MBM1 : MBM0);
        }
        // tail: free buffer (ch+1)&1 (MMA(ch-1) done; precedes just-issued MMA(ch)
        // in the in-order tcgen05 queue so this wait is nearly free), then issue
        // W copies for chunk ch+1 with a full iteration of lead time.
        if (ch < 15) {
            if (ch >= 1) MBAR_WAIT(((ch + 1) & 1) ? MBM1 : MBM0, ((ch - 1) >> 1) & 1);
            if (tid == 0) {
                const uint32_t BUFn = sb + 1024 + (uint32_t)((ch + 1) & 1) * 49152;
                const uint32_t mw = ((ch + 1) & 1) ? MBW1 : MBW0;
                MBAR_EXPECT(mw, 32768);
                BULK_CP(BUFn + 16384, wbh + (size_t)(ch + 1) * 4096, 16384, mw);
                BULK_CP(BUFn + 32768, wbl + (size_t)(ch + 1) * 4096, 16384, mw);
            }
        }
    }
    MBAR_WAIT(MBM1, 1);
    TC_FENCE_AFTER();
    {
        const int m = bm + ((wid & 3) << 5) + lid;
        const int b = m >> 11, s = m & 2047;
#pragma unroll
        for (int cc = 0; cc < 2; cc++) {
            const int c0 = ((wid >> 2) << 6) + cc * 32;
            uint32_t r[32];
            LDTM32(r, tb + c0);
            TCGEN05_WAIT_LD();
            if (MODE == 0) {
                float* out = (float*)outv;
#pragma unroll
                for (int j = 0; j < 32; j += 4) {
                    const int n = bn + c0 + j;
                    float4 v;
                    v.x = __uint_as_float(r[j + 0]) + bias[n + 0];
                    v.y = __uint_as_float(r[j + 1]) + bias[n + 1];
                    v.z = __uint_as_float(r[j + 2]) + bias[n + 2];
                    v.w = __uint_as_float(r[j + 3]) + bias[n + 3];
                    *(float4*)(out + (size_t)m * 512 + n) = v;
                }
            } else if (MODE == 5) {
                uint32_t* qt = (uint32_t*)outv;
                const float qs = 0.125f * 1.44269504088896f;
#pragma unroll
                for (int j = 0; j < 32; j += 4) {
                    const int n = bn + c0 + j;
                    const int hh = n >> 6, dk = n & 63;
                    uint4 u;
                    u.x = f2tf32((__uint_as_float(r[j + 0]) + bias[n + 0]) * qs);
                    u.y = f2tf32((__uint_as_float(r[j + 1]) + bias[n + 1]) * qs);
                    u.z = f2tf32((__uint_as_float(r[j + 2]) + bias[n + 2]) * qs);
                    u.w = f2tf32((__uint_as_float(r[j + 3]) + bias[n + 3]) * qs);
                    *(uint4*)(qt + (((size_t)(b * 8 + hh) * 2048 + s) << 6) + dk) = u;
                }
            } else if (MODE == 3) {
                uint32_t* kt = (uint32_t*)outv;
                const int tile = s >> 7, rr = s & 127;
#pragma unroll
                for (int j = 0; j < 32; j += 4) {
                    const int n = bn + c0 + j;
                    const int hh = n >> 6, dk = n & 63;
                    uint4 u;
                    u.x = f2tf32(__uint_as_float(r[j + 0]) + bias[n + 0]);
                    u.y = f2tf32(__uint_as_float(r[j + 1]) + bias[n + 1]);
                    u.z = f2tf32(__uint_as_float(r[j + 2]) + bias[n + 2]);
                    u.w = f2tf32(__uint_as_float(r[j + 3]) + bias[n + 3]);
                    *(uint4*)(kt + ((size_t)((b * 8 + hh) * 16 + tile) << 13)
                                 + (SWZ(blk_off(rr, dk, 16)) >> 2)) = u;
                }
            } else {  // MODE 4: V
                uint32_t* vt = (uint32_t*)outv;
                const int tile = s >> 7, colv = s & 127;
#pragma unroll
                for (int j = 0; j < 32; j++) {
                    const int n = bn + c0 + j;
                    const int hh = n >> 6, dk = n & 63;
                    vt[((size_t)((b * 8 + hh) * 16 + tile) << 13)
                       + (SWZ(blk_off(dk, colv, 8)) >> 2)] =
                        f2tf32(__uint_as_float(r[j]) + bias[n]);
                }
            }
        }
    }
    TC_FENCE_BEFORE();
    __syncthreads();
    if (tid == 0) { MBAR_INVAL(MBM0); MBAR_INVAL(MBM1); MBAR_INVAL(MBW0); MBAR_INVAL(MBW1); }
    __syncthreads();
    if (wid == 0) TCGEN05_DEALLOC(tb, 128);
}
#endif  // HAS_TC

#if !HAS_TC
__device__ __forceinline__ void gemm_core_fb(
    const float* __restrict__ A, const float* __restrict__ W,
    const float* __restrict__ bias, float* __restrict__ out,
    int MODE, float* smf, int bm, int bn)
{
    float* As = smf;
    float* Bs = smf + 128 * 17;
    const int tid = threadIdx.x;
    const int r0 = (tid >> 4) * 8, c0 = (tid & 15) * 8;
    float acc[8][8];
#pragma unroll
    for (int i = 0; i < 8; i++)
#pragma unroll
        for (int j = 0; j < 8; j++) acc[i][j] = 0.f;
    for (int k0 = 0; k0 < 512; k0 += 16) {
#pragma unroll
        for (int t = 0; t < 8; t++) {
            int lin = tid + t * 256;
            int r = lin >> 4, k = lin & 15;
            As[r * 17 + k] = A[(size_t)(bm + r) * 512 + k0 + k];
            Bs[r * 17 + k] = W[(size_t)(bn + r) * 512 + k0 + k];
        }
        __syncthreads();
#pragma unroll
        for (int k = 0; k < 16; k++) {
            float a8[8], b8[8];
#pragma unroll
            for (int i = 0; i < 8; i++) a8[i] = As[(r0 + i) * 17 + k];
#pragma unroll
            for (int j = 0; j < 8; j++) b8[j] = Bs[(c0 + j) * 17 + k];
#pragma unroll
            for (int i = 0; i < 8; i++)
#pragma unroll
                for (int j = 0; j < 8; j++) acc[i][j] = fmaf(a8[i], b8[j], acc[i][j]);
        }
        __syncthreads();
    }
#pragma unroll
    for (int i = 0; i < 8; i++) {
        int m = bm + r0 + i;
#pragma unroll
        for (int j = 0; j < 8; j++) {
            int n = bn + c0 + j;
            float v = acc[i][j] + bias[n];
            if (MODE == 0) out[(size_t)m * 512 + n] = v;
            else {
                int b = m >> 11, s = m & 2047, h = n >> 6, dk = n & 63;
                if (MODE == 1) out[(((size_t)(b * 8 + h) * 2048 + s) << 6) + dk] = v;
                else           out[((size_t)(b * 8 + h) * 64 + dk) * 2048 + s] = v;
            }
        }
    }
}
#endif

__global__ __launch_bounds__(256) void gemm_qkv(
    const float* __restrict__ x, const float* __restrict__ c,
    const float* __restrict__ Wq, const float* __restrict__ bq,
    const float* __restrict__ Wk, const float* __restrict__ bk,
    const float* __restrict__ Wv, const float* __restrict__ bv,
    const uint32_t* __restrict__ whi, const uint32_t* __restrict__ wlo,
    float* __restrict__ qp, float* __restrict__ kp, float* __restrict__ vp,
    uint32_t* __restrict__ qt, uint32_t* __restrict__ kt, uint32_t* __restrict__ vtt)
{
    const int z = blockIdx.z;
    const float* A = (z == 0) ? x : c;
    const float* bias = (z == 0) ? bq : (z == 1) ? bk : bv;
#if HAS_TC
    void* out = (z == 0) ? (void*)qt : (z == 1) ? (void*)kt : (void*)vtt;
    const int MODE = (z == 0) ? 5 : (z == 1) ? 3 : 4;
    extern __shared__ char sm[];
    gemm_core_tc(A, whi + (size_t)z * 262144, wlo + (size_t)z * 262144,
                 bias, out, MODE, sm, blockIdx.x * 128, blockIdx.y * 128);
#else
    const float* W = (z == 0) ? Wq : (z == 1) ? Wk : Wv;
    float* out = (z == 0) ? qp : (z == 1) ? kp : vp;
    const int MODE = (z == 2) ? 2 : 1;
    extern __shared__ float smf[];
    gemm_core_fb(A, W, bias, out, MODE, smf, blockIdx.x * 128, blockIdx.y * 128);
#endif
}

__global__ __launch_bounds__(256) void gemm_o(
    const float* __restrict__ A, const float* __restrict__ W,
    const uint32_t* __restrict__ whi, const uint32_t* __restrict__ wlo,
    const float* __restrict__ bias, float* __restrict__ out)
{
#if HAS_TC
    extern __shared__ char sm[];
    gemm_core_tc(A, whi + (size_t)3 * 262144, wlo + (size_t)3 * 262144,
                 bias, out, 0, sm, blockIdx.x * 128, blockIdx.y * 128);
#else
    extern __shared__ float smf[];
    gemm_core_fb(A, W, bias, out, 0, smf, blockIdx.x * 128, blockIdx.y * 128);
#endif
}

// ===================== attention (split-S + exp2; best measured) =====================
// TMEM (256): Q 0-63 | S/P in-place 64-191 | O 192-255
__global__ __launch_bounds__(256, 2) void attn_tf32(
    const float* __restrict__ rel,
    const uint32_t* __restrict__ qt, const uint32_t* __restrict__ kt,
    const uint32_t* __restrict__ vtt,
    const float* __restrict__ Qg, const float* __restrict__ Kg,
    const float* __restrict__ Vtg, float* __restrict__ AO)
{
#if HAS_TC
    extern __shared__ char sm[];
    const uint32_t sb = smem_to_u32(sm);
    const int tid = threadIdx.x, wid = tid >> 5, lid = tid & 31;
    const int lg = wid & 3, half = wid >> 2;
    const int q0 = blockIdx.x * 128, bh = blockIdx.y, h = bh & 7;
    const uint32_t MBS0 = sb + 8, MBS1 = sb + 16, MBPV = sb + 24;
    const uint32_t MBK0 = sb + 32, MBK1 = sb + 40, MBV = sb + 48;
    float* bias_f = (float*)(sm + 64);
    const uint32_t KB0 = sb + 2048, KB1 = KB0 + 32768, VB = KB1 + 32768;
    const uint32_t ID_S64 = idesc_tf32(128, 64), ID_PV = idesc_tf32(128, 64);
    const int QB = 0, SPB = 64, OB = 192;

    if (wid == 0) { TCGEN05_ALLOC(sb, 256); TCGEN05_RELINQ(); }
    if (tid == 0) {
        MBAR_INIT(MBS0, 1); MBAR_INIT(MBS1, 1); MBAR_INIT(MBPV, 1);
        MBAR_INIT(MBK0, 1); MBAR_INIT(MBK1, 1); MBAR_INIT(MBV, 1);
    }
    __syncthreads();
    uint32_t tb;
    asm volatile("ld.shared.b32 %0, [%1];" : "=r"(tb) : "r"(sb));

    const uint32_t* ktb = kt + ((size_t)bh * 16 << 13);
    const uint32_t* vtb = vtt + ((size_t)bh * 16 << 13);

    if (tid == 0) {
        MBAR_EXPECT(MBK0, 32768);
        BULK_CP(KB0, ktb, 32768, MBK0);
        MBAR_EXPECT(MBV, 32768);
        BULK_CP(VB, vtb, 32768, MBV);
    }
    if (tid < 128) {                                  // Q -> TMEM (prescaled, log2e folded)
        const uint32_t* qrow = qt + (((size_t)bh * 2048 + q0 + tid) << 6);
        uint32_t qh[32];
#pragma unroll
        for (int p = 0; p < 2; p++) {
#pragma unroll
            for (int j4 = 0; j4 < 8; j4++)
                *(uint4*)(qh + j4 * 4) = *(const uint4*)(qrow + p * 32 + j4 * 4);
            STTM32(tb + QB + p * 32 + ((uint32_t)(tid >> 5) << 21), qh);
        }
        TCGEN05_WAIT_ST();
    }
    TC_FENCE_BEFORE();
    __syncthreads();

    float l_acc = 0.f;
    const int qr = lg * 32 + lid;

    for (int t = 0; t < 16; t++) {
        for (int u = tid; u < 255; u += 256)
            bias_f[u] = rel[(size_t)(q0 - t * 128 + 1920 + u) * 8 + h] * 1.44269504088896f;

        MBAR_WAIT((t & 1) ? MBK1 : MBK0, (t >> 1) & 1);
        if (wid == 0 && elect_one_pred()) {           // split S: two N=64 halves
            TC_FENCE_AFTER();
            uint64_t kd = MAKE_DESC((t & 1) ? KB1 : KB0);
#pragma unroll
            for (int ks = 0; ks < 8; ks++) {
                uint64_t ko = (uint64_t)((ks >> 2) * 1024 + (ks & 3) * 2);
                mma_ts(tb + SPB, tb + QB + ks * 8, kd + ko, ID_S64, ks ? 1u : 0u);
            }
            TCGEN05_COMMIT(MBS0);
#pragma unroll
            for (int ks = 0; ks < 8; ks++) {
                uint64_t ko = (uint64_t)((ks >> 2) * 1024 + (ks & 3) * 2);
                mma_ts(tb + SPB + 64, tb + QB + ks * 8, kd + 512 + ko, ID_S64, ks ? 1u : 0u);
            }
            TCGEN05_COMMIT(MBS1);
        }
        if (tid == 0 && t < 15) {
            const uint32_t KBn = ((t + 1) & 1) ? KB1 : KB0;
            MBAR_EXPECT(((t + 1) & 1) ? MBK1 : MBK0, 32768);
            BULK_CP(KBn, ktb + ((size_t)(t + 1) << 13), 32768, ((t + 1) & 1) ? MBK1 : MBK0);
        }
        if (t > 0) {
            MBAR_WAIT(MBPV, (t - 1) & 1);
            if (tid == 0) {
                MBAR_EXPECT(MBV, 32768);
                BULK_CP(VB, vtb + ((size_t)t << 13), 32768, MBV);
            }
        }
        __syncthreads();

        MBAR_WAIT(half ? MBS1 : MBS0, t & 1);
        TC_FENCE_AFTER();
#pragma unroll
        for (int cc = 0; cc < 2; cc++) {
            const int c = half * 2 + cc;
            uint32_t r[32];
            LDTM32(r, tb + SPB + 32 * c);
            TCGEN05_WAIT_LD();
            uint32_t pr[32];
#pragma unroll
            for (int j = 0; j < 32; j++) {
                float s = __uint_as_float(r[j]) + bias_f[qr - (32 * c + j) + 127];
                float p = exp2f(s);
                l_acc += p;
                pr[j] = f2tf32(p);
            }
            STTM32(tb + SPB + 32 * c + ((uint32_t)lg << 21), pr);
        }
        TCGEN05_WAIT_ST();
        TC_FENCE_BEFORE();
        __syncthreads();

        MBAR_WAIT(MBV, t & 1);
        if (wid == 0 && elect_one_pred()) {
            TC_FENCE_AFTER();
            uint64_t vd = MAKE_DESC(VB);
#pragma unroll
            for (int ks = 0; ks < 16; ks++) {
                uint64_t vo = (uint64_t)((ks >> 2) * 512 + (ks & 3) * 2);
                mma_ts(tb + OB, tb + SPB + ks * 8, vd + vo, ID_PV, (t == 0 && ks == 0) ? 0u : 1u);
            }
            TCGEN05_COMMIT(MBPV);
        }
    }
    MBAR_WAIT(MBPV, 1);

    __syncthreads();
    float* l_sh = (float*)(sm + 64);
    l_sh[tid] = l_acc;
    __syncthreads();
    const float inv = 1.0f / (l_sh[tid & 127] + l_sh[(tid & 127) + 128]);

    TC_FENCE_AFTER();
    {
        uint32_t r[32];
        LDTM32(r, tb + OB + 32 * half);
        TCGEN05_WAIT_LD();
        const int b = bh >> 3;
        float* dst = AO + ((size_t)b * 2048 + q0 + qr) * 512 + h * 64 + 32 * half;
#pragma unroll
        for (int j = 0; j < 32; j++) dst[j] = __uint_as_float(r[j]) * inv;
    }
    TC_FENCE_BEFORE();
    __syncthreads();
    if (tid == 0) {
        MBAR_INVAL(MBS0); MBAR_INVAL(MBS1); MBAR_INVAL(MBPV);
        MBAR_INVAL(MBK0); MBAR_INVAL(MBK1); MBAR_INVAL(MBV);
    }
    __syncthreads();
    if (wid == 0) TCGEN05_DEALLOC(tb, 256);
#else
    // -------- fallback: fp32 flash, two 64-row halves --------
    extern __shared__ float smf[];
    float* Qs = smf;
    float* Ks = Qs + 64 * 68;
    float* Vs = Ks + 64 * 68;
    float* Ps = Vs + 64 * 64;
    float* bias_s = Ps + 64 * 64;
    const int tid = threadIdx.x;
    const int bh = blockIdx.y, h = bh & 7, bb = bh >> 3;
    const int tr = tid >> 4, tc = tid & 15;
    const int r0 = tr * 4, c0 = tc * 4;

    for (int hf = 0; hf < 2; hf++) {
        const int q0 = blockIdx.x * 128 + hf * 64;
        const float* Qbase = Qg + ((size_t)bh * 2048 + q0) * 64;
        const float* Kbase = Kg + (size_t)bh * 2048 * 64;
#pragma unroll
        for (int t = 0; t < 4; t++) {
            int lin = tid + t * 256;
            int r = lin >> 4, kc2 = (lin & 15) << 2;
            float4 v = *(const float4*)(Qbase + r * 64 + kc2);
            v.x *= 0.125f; v.y *= 0.125f; v.z *= 0.125f; v.w *= 0.125f;
            *(float4*)(Qs + r * 68 + kc2) = v;
        }
        float m_i[4], l_i[4], o[4][4];
#pragma unroll
        for (int i = 0; i < 4; i++) {
            m_i[i] = -1e30f; l_i[i] = 0.f;
#pragma unroll
            for (int d = 0; d < 4; d++) o[i][d] = 0.f;
        }
        for (int t = 0; t < 32; t++) {
            const int ck0 = t * 64;
#pragma unroll
            for (int tt = 0; tt < 4; tt++) {
                int lin = tid + tt * 256;
                int r = lin >> 4, kc2 = (lin & 15) << 2;
                float4 kv = *(const float4*)(Kbase + (size_t)(ck0 + r) * 64 + kc2);
                *(float4*)(Ks + r * 68 + kc2) = kv;
            }
#pragma unroll
            for (int tt = 0; tt < 16; tt++) {
                int lin = tid + tt * 256;
                int r = lin & 63, cdk = lin >> 6;
                Vs[r * 64 + cdk] = Vtg[((size_t)bh * 64 + cdk) * 2048 + ck0 + r];
            }
            if (tid < 127)
                bias_s[tid] = rel[(size_t)(q0 - ck0 + 1984 + tid) * 8 + h];
            __syncthreads();

            float s[4][4];
#pragma unroll
            for (int i = 0; i < 4; i++)
#pragma unroll
                for (int j = 0; j < 4; j++) s[i][j] = 0.f;
#pragma unroll
            for (int k = 0; k < 64; k += 4) {
                float4 a4[4], b4[4];
#pragma unroll
                for (int i = 0; i < 4; i++) a4[i] = *(const float4*)(Qs + (r0 + i) * 68 + k);
#pragma unroll
                for (int j = 0; j < 4; j++) b4[j] = *(const float4*)(Ks + (c0 + j) * 68 + k);
#pragma unroll
                for (int i = 0; i < 4; i++)
#pragma unroll
                    for (int j = 0; j < 4; j++) {
                        s[i][j] = fmaf(a4[i].x, b4[j].x, s[i][j]);
                        s[i][j] = fmaf(a4[i].y, b4[j].y, s[i][j]);
                        s[i][j] = fmaf(a4[i].z, b4[j].z, s[i][j]);
                        s[i][j] = fmaf(a4[i].w, b4[j].w, s[i][j]);
                    }
            }
#pragma unroll
            for (int i = 0; i < 4; i++) {
                int bi = 63 + (r0 + i) - c0;
                s[i][0] += bias_s[bi];   s[i][1] += bias_s[bi - 1];
                s[i][2] += bias_s[bi - 2]; s[i][3] += bias_s[bi - 3];
                float rmax = fmaxf(fmaxf(s[i][0], s[i][1]), fmaxf(s[i][2], s[i][3]));
#pragma unroll
                for (int off = 8; off >= 1; off >>= 1)
                    rmax = fmaxf(rmax, __shfl_xor_sync(0xffffffffu, rmax, off));
                float m_new = fmaxf(m_i[i], rmax);
                float corr = __expf(m_i[i] - m_new);
                m_i[i] = m_new;
                float p0 = __expf(s[i][0] - m_new), p1 = __expf(s[i][1] - m_new);
                float p2 = __expf(s[i][2] - m_new), p3 = __expf(s[i][3] - m_new);
                float rsum = (p0 + p1) + (p2 + p3);
#pragma unroll
                for (int off = 8; off >= 1; off >>= 1)
                    rsum += __shfl_xor_sync(0xffffffffu, rsum, off);
                l_i[i] = l_i[i] * corr + rsum;
                o[i][0] *= corr; o[i][1] *= corr; o[i][2] *= corr; o[i][3] *= corr;
                *(float4*)(Ps + (r0 + i) * 64 + c0) = make_float4(p0, p1, p2, p3);
            }
            __syncthreads();
#pragma unroll
            for (int j = 0; j < 64; j += 4) {
                float4 p4[4], v4[4];
#pragma unroll
                for (int i = 0; i < 4; i++) p4[i] = *(const float4*)(Ps + (r0 + i) * 64 + j);
#pragma unroll
                for (int jj = 0; jj < 4; jj++) v4[jj] = *(const float4*)(Vs + (j + jj) * 64 + c0);
#pragma unroll
                for (int i = 0; i < 4; i++) {
                    o[i][0] = fmaf(p4[i].x, v4[0].x, o[i][0]); o[i][1] = fmaf(p4[i].x, v4[0].y, o[i][1]);
                    o[i][2] = fmaf(p4[i].x, v4[0].z, o[i][2]); o[i][3] = fmaf(p4[i].x, v4[0].w, o[i][3]);
                    o[i][0] = fmaf(p4[i].y, v4[1].x, o[i][0]); o[i][1] = fmaf(p4[i].y, v4[1].y, o[i][1]);
                    o[i][2] = fmaf(p4[i].y, v4[1].z, o[i][2]); o[i][3] = fmaf(p4[i].y, v4[1].w, o[i][3]);
                    o[i][0] = fmaf(p4[i].z, v4[2].x, o[i][0]); o[i][1] = fmaf(p4[i].z, v4[2].y, o[i][1]);
                    o[i][2] = fmaf(p4[i].z, v4[2].z, o[i][2]); o[i][3] = fmaf(p4[i].z, v4[2].w, o[i][3]);
                    o[i][0] = fmaf(p4[i].w, v4[3].x, o[i][0]); o[i][1] = fmaf(p4[i].w, v4[3].y, o[i][1]);
                    o[i][2] = fmaf(p4[i].w, v4[3].z, o[i][2]); o[i][3] = fmaf(p4[i].w, v4[3].w, o[i][3]);
                }
            }
            __syncthreads();
        }
        float* AObase = AO + ((size_t)bb * 2048 + q0) * 512 + h * 64;
#pragma unroll
        for (int i = 0; i < 4; i++) {
            float inv = 1.0f / l_i[i];
            *(float4*)(AObase + (size_t)(r0 + i) * 512 + c0) =
                make_float4(o[i][0] * inv, o[i][1] * inv, o[i][2] * inv, o[i][3] * inv);
        }
        __syncthreads();
    }
#endif
}

// ===========================================================================
extern "C" void kernel_launch(void* const* d_in, const int* in_sizes, int n_in,
                              void* d_out, int out_size)
{
    const float* x   = (const float*)d_in[0];
    const float* c   = (const float*)d_in[1];
    const float* Wq  = (const float*)d_in[2];
    const float* bq  = (const float*)d_in[3];
    const float* Wk  = (const float*)d_in[4];
    const float* bk  = (const float*)d_in[5];
    const float* Wv  = (const float*)d_in[6];
    const float* bv  = (const float*)d_in[7];
    const float* Wo  = (const float*)d_in[8];
    const float* bo  = (const float*)d_in[9];
    const float* rel = (const float*)d_in[10];
    float* out = (float*)d_out;

    float *qp, *kp, *vp, *aop;
    uint32_t *whi, *wlo, *qt, *kt, *vtt;
    cudaGetSymbolAddress((void**)&qp,  g_Q);
    cudaGetSymbolAddress((void**)&kp,  g_K);
    cudaGetSymbolAddress((void**)&vp,  g_Vt);
    cudaGetSymbolAddress((void**)&aop, g_AO);
    cudaGetSymbolAddress((void**)&whi, g_Whi);
    cudaGetSymbolAddress((void**)&wlo, g_Wlo);
    cudaGetSymbolAddress((void**)&qt,  g_Qt);
    cudaGetSymbolAddress((void**)&kt,  g_Kt);
    cudaGetSymbolAddress((void**)&vtt, g_Vtt);

    const int smem_gemm = 1024 + 2 * 49152;            // 99328
    const int smem_attn = 2048 + 3 * 32768;            // 100352 (fallback needs 68096)
    cudaFuncSetAttribute(gemm_qkv, cudaFuncAttributeMaxDynamicSharedMemorySize, smem_gemm);
    cudaFuncSetAttribute(gemm_o,   cudaFuncAttributeMaxDynamicSharedMemorySize, smem_gemm);
    cudaFuncSetAttribute(attn_tf32, cudaFuncAttributeMaxDynamicSharedMemorySize, smem_attn);

    presplit_w<<<dim3(128, 4), 256>>>(Wq, Wk, Wv, Wo, whi, wlo);
    gemm_qkv<<<dim3(64, 4, 3), 256, smem_gemm>>>(x, c, Wq, bq, Wk, bk, Wv, bv,
                                                 whi, wlo, qp, kp, vp, qt, kt, vtt);
    attn_tf32<<<dim3(16, 32), 256, smem_attn>>>(rel, qt, kt, vtt, qp, kp, vp, aop);
    gemm_o<<<dim3(64, 4), 256, smem_gemm>>>(aop, Wo, whi, wlo, bo, out);
}